// round 13
// baseline (speedup 1.0000x reference)
#include <cuda_runtime.h>

#define NB   16384
#define NH   1024
#define NIN  32
#define NU   10
#define MI   138
#define ITER 30
#define SIGMA 0.1f
#define FC1_BLOCKS 128
#define FC2_BLOCKS (NB/32)    // 512

#define IPB  16               // items per IPM block (32 threads, 2 per item)
#define SROW 129              // odd stride -> conflict-free pair access

typedef unsigned long long u64;

// ---------------- device scratch (static, no allocs) ----------------
__device__ float g_h1[NB*NH];              // 64 MB, row-major [item][feature]
__device__ float g_bn1p[FC1_BLOCKS*NH];
__device__ float g_bn1q[FC1_BLOCKS*NH];
__device__ float g_W2f[NU*NH];
__device__ float g_b2f[NU];
__device__ float g_t2[NB*NU];
__device__ float g_bn2p[FC2_BLOCKS*NU];
__device__ float g_bn2q[FC2_BLOCKS*NU];
__device__ float g_Qhat[NU*NU];
__device__ float g_G[MI*NU];
__device__ float g_h[MI];

__device__ __forceinline__ float frcp(float x){ float r; asm("rcp.approx.f32 %0, %1;" : "=f"(r) : "f"(x)); return r; }
__device__ __forceinline__ float lrelu(float v){ return v > 0.f ? v : 0.2f*v; }

// ---- packed f32x2 helpers ----
__device__ __forceinline__ u64 pk(float x, float y){
    u64 r; asm("mov.b64 %0, {%1,%2};" : "=l"(r) : "f"(x), "f"(y)); return r;
}
__device__ __forceinline__ void upk(u64 v, float& x, float& y){
    asm("mov.b64 {%0,%1}, %2;" : "=f"(x), "=f"(y) : "l"(v));
}
__device__ __forceinline__ u64 fma2(u64 a, u64 b, u64 c){
    u64 d; asm("fma.rn.f32x2 %0, %1, %2, %3;" : "=l"(d) : "l"(a), "l"(b), "l"(c)); return d;
}
__device__ __forceinline__ u64 mul2(u64 a, u64 b){
    u64 d; asm("mul.rn.f32x2 %0, %1, %2;" : "=l"(d) : "l"(a), "l"(b)); return d;
}
__device__ __forceinline__ u64 add2(u64 a, u64 b){
    u64 d; asm("add.rn.f32x2 %0, %1, %2;" : "=l"(d) : "l"(a), "l"(b)); return d;
}
__device__ __forceinline__ u64 sh64(u64 v){
    return __shfl_xor_sync(0xffffffffu, v, 1);
}

// ---------------- K0: fc1 (blocks 0..127) + build_qp (block 128) ----------------
__global__ void __launch_bounds__(256) fc1qp_kernel(
    const float* __restrict__ x,  const float* __restrict__ W1, const float* __restrict__ b1,
    const float* __restrict__ L,  const float* __restrict__ LP, const float* __restrict__ LR,
    const float* __restrict__ A,  const float* __restrict__ Bm,
    const float* __restrict__ u0, const float* __restrict__ s0)
{
    __shared__ __align__(16) float sh[5120];
    const int t = threadIdx.x;

    if (blockIdx.x < 128){
        // ================= fc1 =================
        float* xs = sh;
        const int row0 = blockIdx.x * 128;
        {
            const float4* src = (const float4*)(x + row0*32);
            float4* dst = (float4*)xs;
            for (int e = t; e < 1024; e += 256) dst[e] = src[e];
        }
        __syncthreads();
        #pragma unroll
        for (int ff = 0; ff < 4; ff++){
            const int f = t + ff*256;
            float w[32];
            const float4* wp = (const float4*)(W1 + f*32);
            #pragma unroll
            for (int k = 0; k < 8; k++){
                float4 v = wp[k];
                w[4*k+0]=v.x; w[4*k+1]=v.y; w[4*k+2]=v.z; w[4*k+3]=v.w;
            }
            const float bias = b1[f];
            float sum = 0.f, sq = 0.f;
            for (int r = 0; r < 128; r++){
                float acc = bias;
                const float4* xp = (const float4*)(xs + r*32);
                #pragma unroll
                for (int k = 0; k < 8; k++){
                    float4 xv = xp[k];
                    acc = fmaf(xv.x, w[4*k+0], acc);
                    acc = fmaf(xv.y, w[4*k+1], acc);
                    acc = fmaf(xv.z, w[4*k+2], acc);
                    acc = fmaf(xv.w, w[4*k+3], acc);
                }
                float v = lrelu(acc);
                g_h1[(row0+r)*NH + f] = v;
                sum += v; sq = fmaf(v, v, sq);
            }
            g_bn1p[blockIdx.x*NH + f] = sum;
            g_bn1q[blockIdx.x*NH + f] = sq;
        }
        return;
    }

    // ================= build_qp (block 128) =================
    float* Q  = sh;            // 1024
    float* P  = sh + 1024;     // 1024
    float* Bh = sh + 2048;     // 1280
    float* Ms = sh + 3328;     // 1280
    float* pw = sh + 4608;     // 256 (4 x 64)
    float* R  = sh + 4864;     // 4

    for (int e = t; e < 1024; e += 256){
        int i = e >> 5, j = e & 31;
        int kmax = i < j ? i : j;
        float aq = (i==j) ? 1e-4f : 0.f;
        float ap = aq;
        for (int k = 0; k <= kmax; k++){
            aq = fmaf(L [i*32+k], L [j*32+k], aq);
            ap = fmaf(LP[i*32+k], LP[j*32+k], ap);
        }
        Q[e] = aq; P[e] = ap;
    }
    if (t < 4){
        int i = t >> 1, j = t & 1;
        int kmax = i < j ? i : j;
        float a = (i==j) ? 1e-4f : 0.f;
        for (int k = 0; k <= kmax; k++) a = fmaf(LR[i*2+k], LR[j*2+k], a);
        R[t] = a;
    }
    if (t < 64) pw[t] = Bm[t];
    __syncthreads();
    for (int s = 1; s < 4; s++){
        if (t < 64){
            int r = t >> 1, c = t & 1;
            float acc = 0.f;
            for (int k = 0; k < 32; k++) acc = fmaf(A[r*32+k], pw[(s-1)*64 + k*2+c], acc);
            pw[s*64 + t] = acc;
        }
        __syncthreads();
    }
    for (int e = t; e < 128*NU; e += 256){
        int row = e / NU, col = e - row*NU;
        int bi = row >> 5, r = row & 31, bj = col >> 1, c = col & 1;
        Bh[e] = (bj <= bi) ? pw[(bi-bj)*64 + r*2+c] : 0.f;
    }
    __syncthreads();
    for (int e = t; e < 128*NU; e += 256){
        int row = e / NU, col = e - row*NU;
        int b = row >> 5, r = row & 31;
        const float* Qb = (b < 3) ? Q : P;
        float acc = 0.f;
        for (int k = 0; k < 32; k++) acc = fmaf(Qb[r*32+k], Bh[(b*32+k)*NU+col], acc);
        Ms[e] = acc;
    }
    __syncthreads();
    if (t < 100){
        int a = t / NU, b = t - (t/NU)*NU;
        float acc = ((a>>1) == (b>>1)) ? R[(a&1)*2+(b&1)] : 0.f;
        for (int row = 0; row < 128; row++) acc = fmaf(Bh[row*NU+a], Ms[row*NU+b], acc);
        g_Qhat[t] = acc;
    }
    for (int e = t; e < MI*NU; e += 256){
        int row = e / NU, col = e - (e/NU)*NU;
        g_G[e] = (row < NU) ? ((row==col) ? 1.f : 0.f) : Bh[(row-NU)*NU+col];
    }
    if (t < MI){
        float acc = s0[t];
        if (t < NU) acc += u0[t];
        else { for (int j = 0; j < NU; j++) acc = fmaf(Bh[(t-NU)*NU+j], u0[j], acc); }
        g_h[t] = acc;
    }
}

// ---------------- K1: bn1 finalize fused with fc2-weight fold ----------------
__global__ void fold_all(const float* __restrict__ W2, const float* __restrict__ b2,
                         const float* __restrict__ g1, const float* __restrict__ beta1)
{
    __shared__ float red[256];
    const int u = blockIdx.x, t = threadIdx.x;
    float dot = 0.f;
    for (int k = t; k < NH; k += 256){
        float sum = 0.f, sq = 0.f;
        for (int b = 0; b < FC1_BLOCKS; b++){
            sum += g_bn1p[b*NH + k];
            sq  += g_bn1q[b*NH + k];
        }
        float mu  = sum * (1.f/(float)NB);
        float var = sq  * (1.f/(float)NB) - mu*mu;
        float a = g1[k]*rsqrtf(var + 1e-5f);
        float c = beta1[k] - mu*a;
        float wv = W2[u*NH + k];
        g_W2f[u*NH + k] = wv * a;
        dot = fmaf(wv, c, dot);
    }
    red[t] = dot; __syncthreads();
    for (int s = 128; s > 0; s >>= 1){
        if (t < s) red[t] += red[t+s];
        __syncthreads();
    }
    if (t == 0) g_b2f[u] = b2[u] + red[0];
}

// ---------------- K2: fc2 (4 items per warp) + leaky_relu + bn2 stats ----------------
__global__ void __launch_bounds__(256) fc2_kernel()
{
    __shared__ float Ws[NU*NH];
    __shared__ float bs[NU];
    __shared__ float wt2[32][NU];
    const int t = threadIdx.x, lane = t & 31, wid = t >> 5;
    for (int e = t; e < NU*NH; e += 256) Ws[e] = g_W2f[e];
    if (t < NU) bs[t] = g_b2f[t];
    __syncthreads();
    const int item0 = blockIdx.x*32 + wid*4;
    float acc0[NU], acc1[NU], acc2[NU], acc3[NU];
    #pragma unroll
    for (int u = 0; u < NU; u++){ acc0[u]=0.f; acc1[u]=0.f; acc2[u]=0.f; acc3[u]=0.f; }
    const float* h0 = g_h1 + item0*NH;
    const float* h1r = h0 + NH;
    const float* h2r = h0 + 2*NH;
    const float* h3r = h0 + 3*NH;
    for (int j = 0; j < 32; j++){
        float v0 = h0[j*32 + lane];
        float v1 = h1r[j*32 + lane];
        float v2 = h2r[j*32 + lane];
        float v3 = h3r[j*32 + lane];
        #pragma unroll
        for (int u = 0; u < NU; u++){
            float wv = Ws[u*NH + j*32 + lane];
            acc0[u] = fmaf(v0, wv, acc0[u]);
            acc1[u] = fmaf(v1, wv, acc1[u]);
            acc2[u] = fmaf(v2, wv, acc2[u]);
            acc3[u] = fmaf(v3, wv, acc3[u]);
        }
    }
    #pragma unroll
    for (int u = 0; u < NU; u++){
        #pragma unroll
        for (int off = 16; off > 0; off >>= 1){
            acc0[u] += __shfl_xor_sync(0xffffffffu, acc0[u], off);
            acc1[u] += __shfl_xor_sync(0xffffffffu, acc1[u], off);
            acc2[u] += __shfl_xor_sync(0xffffffffu, acc2[u], off);
            acc3[u] += __shfl_xor_sync(0xffffffffu, acc3[u], off);
        }
    }
    if (lane == 0){
        #pragma unroll
        for (int u = 0; u < NU; u++){
            float v0 = lrelu(acc0[u] + bs[u]);
            float v1 = lrelu(acc1[u] + bs[u]);
            float v2 = lrelu(acc2[u] + bs[u]);
            float v3 = lrelu(acc3[u] + bs[u]);
            g_t2[(item0+0)*NU + u] = v0;
            g_t2[(item0+1)*NU + u] = v1;
            g_t2[(item0+2)*NU + u] = v2;
            g_t2[(item0+3)*NU + u] = v3;
            wt2[wid*4+0][u] = v0;
            wt2[wid*4+1][u] = v1;
            wt2[wid*4+2][u] = v2;
            wt2[wid*4+3][u] = v3;
        }
    }
    __syncthreads();
    if (t < NU){
        float s = 0.f, q = 0.f;
        #pragma unroll
        for (int w = 0; w < 32; w++){ float v = wt2[w][t]; s += v; q = fmaf(v, v, q); }
        g_bn2p[blockIdx.x*NU + t] = s;
        g_bn2q[blockIdx.x*NU + t] = q;
    }
}

// ---------------- K3: batched IPM, 32-thread blocks, rp-recurrence, packed (s,l) ----------------
#define HOFF0 0
#define HOFF1 1
#define HOFF2 2
#define HOFF3 4
#define HOFF4 6
#define HOFF5 9
#define HOFF6 12
#define HOFF7 16
#define HOFF8 20
#define HOFF9 25

template<int K>
__device__ __forceinline__ void passA_blk(const float* __restrict__ Gblk, int sa0, int hBase,
    float phi, u64* H2, u64* b1p, float smu,
    const u64* sl_sh, const float* h_sh)
{
    const int HOFF[10] = {HOFF0,HOFF1,HOFF2,HOFF3,HOFF4,HOFF5,HOFF6,HOFF7,HOFF8,HOFF9};
    const int KH = K/2;
    #pragma unroll 4
    for (int j = 0; j < 16; j++){
        const int sa = sa0 + j;
        float sm, lm; upk(sl_sh[sa], sm, lm);
        float ivs = frcp(sm);
        float w = lm*ivs;
        float rp = phi * h_sh[hBase + j];          // rp = phi*(1-h)
        float coef = fmaf(lm, rp, smu)*ivs;
        float2 gv[KH]; u64 g2[KH];
        #pragma unroll
        for (int jj = 0; jj < KH; jj++){
            gv[jj] = *(const float2*)&Gblk[j*K + 2*jj];
            g2[jj] = pk(gv[jj].x, gv[jj].y);
        }
        u64 w2v = pk(w, w), c2 = pk(coef, coef);
        u64 wgp[KH];
        #pragma unroll
        for (int jj = 0; jj < KH; jj++){
            wgp[jj] = mul2(w2v, g2[jj]);
            b1p[jj] = fma2(c2, g2[jj], b1p[jj]);
        }
        #pragma unroll
        for (int a = 0; a < K; a++){
            float ga = (a & 1) ? gv[a>>1].y : gv[a>>1].x;
            u64 ga2 = pk(ga, ga);
            #pragma unroll
            for (int pi = 0; pi <= (a>>1); pi++)
                H2[HOFF[a]+pi] = fma2(ga2, wgp[pi], H2[HOFF[a]+pi]);
        }
    }
}

template<int K>
__device__ __forceinline__ void passB1_blk(const float* __restrict__ Gblk, int sa0, int hBase,
    const u64* dz2, float phi, float smu, float& q,
    const u64* sl_sh, float* r_sh, const float* h_sh)
{
    const int KH = K/2;
    #pragma unroll 4
    for (int j = 0; j < 16; j++){
        const int sa = sa0 + j;
        float sm, lm; upk(sl_sh[sa], sm, lm);
        u64 acc = pk(0.f, 0.f);
        #pragma unroll
        for (int jj = 0; jj < KH; jj++){
            float2 gvj = *(const float2*)&Gblk[j*K + 2*jj];
            acc = fma2(pk(gvj.x, gvj.y), dz2[jj], acc);
        }
        float gx, gy; upk(acc, gx, gy);
        float ds = -fmaf(phi, h_sh[hBase + j], gx + gy);   // alpha-independent
        r_sh[sa] = ds;
        float ivsl = frcp(sm*lm);
        float r1 = -ds*lm*ivsl;
        float r2 = fmaf(fmaf(ds, lm, -smu), ivsl, 1.f);
        q = fmaxf(q, fmaxf(r1, r2));
    }
}

template<int K>
__device__ __forceinline__ void passB2_blk(int sa0,
    float smu, float alpha, float& msn,
    u64* sl_sh, const float* r_sh)
{
    #pragma unroll 4
    for (int j = 0; j < 16; j++){
        const int sa = sa0 + j;
        float sm, lm; upk(sl_sh[sa], sm, lm);
        float ds = r_sh[sa];
        float rc = fmaf(sm, lm, -smu);
        float ivs = frcp(sm);
        float dlam = -fmaf(lm, ds, rc)*ivs;
        float sn = fmaf(alpha, ds, sm);
        float ln = fmaf(alpha, dlam, lm);
        sl_sh[sa] = pk(sn, ln);
        msn = fmaf(sn, ln, msn);
    }
}

__global__ void __launch_bounds__(32, 7) ipm_kernel(float* __restrict__ out,
    const float* __restrict__ g2, const float* __restrict__ beta2)
{
    extern __shared__ __align__(16) float dyn[];
    u64*   sl_sh = (u64*)dyn;                       // IPB*SROW u64 (s,l packed)
    float* r_sh  = dyn + 2*IPB*SROW;                // IPB*SROW floats (ds cache)
    __shared__ __align__(8) float G_sh[704];
    __shared__ float h_sh[MI];                      // holds (1 - h)
    __shared__ __align__(8) float Q_sh[NU*NU];
    __shared__ float ac_sh[2*NU];
    const int GA[4] = {0, 80, 224, 432};
    const int GB[4] = {48, 160, 336, 576};

    const int tid = threadIdx.x;          // 0..31 (one warp)
    const int r = tid & 1, q = tid >> 1;  // q in 0..15
    const int item = blockIdx.x*IPB + q;

    // ---- preamble: bn2 finalize (redundant per block; warp-shuffle reduce)
    {
        float loc[20];
        #pragma unroll
        for (int j = 0; j < 20; j++) loc[j] = 0.f;
        for (int b = tid; b < FC2_BLOCKS; b += 32){
            #pragma unroll
            for (int u = 0; u < NU; u++){
                loc[u]    += g_bn2p[b*NU + u];
                loc[10+u] += g_bn2q[b*NU + u];
            }
        }
        #pragma unroll
        for (int j = 0; j < 20; j++){
            #pragma unroll
            for (int off = 16; off > 0; off >>= 1)
                loc[j] += __shfl_xor_sync(0xffffffffu, loc[j], off);
        }
        if (tid < NU){
            float sv = 0.f, qv = 0.f;
            #pragma unroll
            for (int u = 0; u < NU; u++){
                if (tid == u){ sv = loc[u]; qv = loc[10+u]; }
            }
            float mu  = sv * (1.f/(float)NB);
            float var = qv * (1.f/(float)NB) - mu*mu;
            float a = g2[tid]*rsqrtf(var + 1e-5f);
            ac_sh[tid]      = a;
            ac_sh[NU + tid] = beta2[tid] - mu*a;
        }
    }

    // loads (32 threads)
    for (int mm = tid; mm < 128; mm += 32){
        int bi = mm >> 5, lr = mm & 31, hf = lr >> 4, j = lr & 15, K = 2*bi + 2;
        int base = (hf ? GB[bi] : GA[bi]) + j*K;
        for (int c = 0; c < K; c++) G_sh[base + c] = g_G[(10+mm)*NU + c];
    }
    for (int i = tid; i < MI; i += 32) h_sh[i] = 1.f - g_h[i];   // (1-h)
    for (int i = tid; i < 100; i += 32) Q_sh[i] = g_Qhat[i];
    __syncthreads();

    float p[NU];
    u64 z2[5];
    #pragma unroll
    for (int u = 0; u < NU; u++)
        p[u] = fmaf(g_t2[item*NU+u], ac_sh[u], ac_sh[NU+u]);
    #pragma unroll
    for (int j = 0; j < 5; j++) z2[j] = pk(0.f, 0.f);

    float s_id[5], l_id[5];
    #pragma unroll
    for (int j = 0; j < 5; j++){ s_id[j] = 1.f; l_id[j] = 1.f; }

    int saB[4], hB[4];
    const float* Gb[4];
    #pragma unroll
    for (int bi = 0; bi < 4; bi++){
        int mm0 = 32*bi + 16*r;
        saB[bi] = q*SROW + mm0;
        hB[bi]  = 10 + mm0;
        Gb[bi]  = &G_sh[r ? GB[bi] : GA[bi]];
        #pragma unroll 4
        for (int j = 0; j < 16; j++)
            sl_sh[saB[bi]+j] = pk(1.f, 1.f);
    }
    float musum = (float)MI;
    float phi = 1.f;                       // prod(1-alpha)

    for (int it = 0; it < ITER; it++){
        float smu = musum * (SIGMA/(float)MI);
        u64 H2[30], b1p[5];
        #pragma unroll
        for (int e = 0; e < 30; e++) H2[e] = pk(0.f, 0.f);
        #pragma unroll
        for (int j = 0; j < 5; j++) b1p[j] = pk(0.f, 0.f);

        // identity rows: compile-time indices per parity branch
        if (r == 0){
            #pragma unroll
            for (int j = 0; j < 5; j++){
                const int m = j;
                float sm = s_id[j], lm = l_id[j];
                float ivs = frcp(sm);
                float w = lm*ivs;
                float rp = phi * h_sh[m];
                float c = fmaf(lm, rp, smu)*ivs;
                b1p[m/2] = add2(b1p[m/2], (m&1) ? pk(0.f,c) : pk(c,0.f));
                const int ho = (m==0?HOFF0:m==1?HOFF1:m==2?HOFF2:m==3?HOFF3:HOFF4) + m/2;
                H2[ho] = add2(H2[ho], (m&1) ? pk(0.f,w) : pk(w,0.f));
            }
        } else {
            #pragma unroll
            for (int j = 0; j < 5; j++){
                const int m = 5 + j;
                float sm = s_id[j], lm = l_id[j];
                float ivs = frcp(sm);
                float w = lm*ivs;
                float rp = phi * h_sh[m];
                float c = fmaf(lm, rp, smu)*ivs;
                b1p[m/2] = add2(b1p[m/2], (m&1) ? pk(0.f,c) : pk(c,0.f));
                const int ho = (m==5?HOFF5:m==6?HOFF6:m==7?HOFF7:m==8?HOFF8:HOFF9) + m/2;
                H2[ho] = add2(H2[ho], (m&1) ? pk(0.f,w) : pk(w,0.f));
            }
        }

        passA_blk<2>(Gb[0], saB[0], hB[0], phi, H2, b1p, smu, sl_sh, h_sh);
        passA_blk<4>(Gb[1], saB[1], hB[1], phi, H2, b1p, smu, sl_sh, h_sh);
        passA_blk<6>(Gb[2], saB[2], hB[2], phi, H2, b1p, smu, sl_sh, h_sh);
        passA_blk<8>(Gb[3], saB[3], hB[3], phi, H2, b1p, smu, sl_sh, h_sh);

        #pragma unroll
        for (int e = 0; e < 30; e++) H2[e] = add2(H2[e], sh64(H2[e]));
        #pragma unroll
        for (int j = 0; j < 5; j++) b1p[j] = add2(b1p[j], sh64(b1p[j]));

        const int HOFF[10] = {HOFF0,HOFF1,HOFF2,HOFF3,HOFF4,HOFF5,HOFF6,HOFF7,HOFF8,HOFF9};
        float Hs[55];
        #pragma unroll
        for (int a = 0; a < NU; a++){
            #pragma unroll
            for (int pi = 0; pi <= (a>>1); pi++){
                float x, y; upk(H2[HOFF[a]+pi], x, y);
                Hs[(a*(a+1))/2 + 2*pi] = x + Q_sh[a*NU + 2*pi];
                if (2*pi+1 <= a) Hs[(a*(a+1))/2 + 2*pi+1] = y + Q_sh[a*NU + 2*pi+1];
            }
        }
        float b1[NU];
        #pragma unroll
        for (int j = 0; j < 5; j++) upk(b1p[j], b1[2*j], b1[2*j+1]);

        float dz[NU];
        #pragma unroll
        for (int i = 0; i < NU; i++){
            u64 acc = pk(0.f, 0.f);
            #pragma unroll
            for (int j = 0; j < 5; j++){
                float2 qv = *(const float2*)&Q_sh[i*NU + 2*j];
                acc = fma2(pk(qv.x, qv.y), z2[j], acc);
            }
            float qx, qy; upk(acc, qx, qy);
            dz[i] = -(p[i] + b1[i] + qx + qy);
        }
        #pragma unroll
        for (int k = 0; k < NU; k++){
            float inv = rsqrtf(Hs[(k*(k+1))/2+k]);
            Hs[(k*(k+1))/2+k] = inv;
            #pragma unroll
            for (int i = k+1; i < NU; i++) Hs[(i*(i+1))/2+k] *= inv;
            #pragma unroll
            for (int j = k+1; j < NU; j++){
                float ljk = Hs[(j*(j+1))/2+k];
                #pragma unroll
                for (int i = j; i < NU; i++)
                    Hs[(i*(i+1))/2+j] = fmaf(-Hs[(i*(i+1))/2+k], ljk, Hs[(i*(i+1))/2+j]);
            }
        }
        #pragma unroll
        for (int i = 0; i < NU; i++){
            float tt = dz[i];
            #pragma unroll
            for (int j = 0; j < i; j++) tt = fmaf(-Hs[(i*(i+1))/2+j], dz[j], tt);
            dz[i] = tt * Hs[(i*(i+1))/2+i];
        }
        #pragma unroll
        for (int i = NU-1; i >= 0; i--){
            float tt = dz[i];
            #pragma unroll
            for (int j = i+1; j < NU; j++) tt = fmaf(-Hs[(j*(j+1))/2+i], dz[j], tt);
            dz[i] = tt * Hs[(i*(i+1))/2+i];
        }
        u64 dz2[5];
        #pragma unroll
        for (int j = 0; j < 5; j++) dz2[j] = pk(dz[2*j], dz[2*j+1]);

        // ---- pass B1: ds cached in r_sh; step-length ratios ----
        float qm = 0.f;
        if (r == 0){
            #pragma unroll
            for (int j = 0; j < 5; j++){
                const int m = j;
                float sm = s_id[j], lm = l_id[j];
                float ds = -fmaf(phi, h_sh[m], dz[m]);
                float ivsl = frcp(sm*lm);
                float r1 = -ds*lm*ivsl;
                float r2 = fmaf(fmaf(ds, lm, -smu), ivsl, 1.f);
                qm = fmaxf(qm, fmaxf(r1, r2));
            }
        } else {
            #pragma unroll
            for (int j = 0; j < 5; j++){
                const int m = 5 + j;
                float sm = s_id[j], lm = l_id[j];
                float ds = -fmaf(phi, h_sh[m], dz[m]);
                float ivsl = frcp(sm*lm);
                float r1 = -ds*lm*ivsl;
                float r2 = fmaf(fmaf(ds, lm, -smu), ivsl, 1.f);
                qm = fmaxf(qm, fmaxf(r1, r2));
            }
        }
        passB1_blk<2>(Gb[0], saB[0], hB[0], dz2, phi, smu, qm, sl_sh, r_sh, h_sh);
        passB1_blk<4>(Gb[1], saB[1], hB[1], dz2, phi, smu, qm, sl_sh, r_sh, h_sh);
        passB1_blk<6>(Gb[2], saB[2], hB[2], dz2, phi, smu, qm, sl_sh, r_sh, h_sh);
        passB1_blk<8>(Gb[3], saB[3], hB[3], dz2, phi, smu, qm, sl_sh, r_sh, h_sh);
        qm = fmaxf(qm, __shfl_xor_sync(0xffffffffu, qm, 1));
        float alpha = fminf(1.f, 0.99f*frcp(qm));

        // ---- pass B2: ds from r_sh; update s/lam; accumulate musum ----
        float msn = 0.f;
        if (r == 0){
            #pragma unroll
            for (int j = 0; j < 5; j++){
                const int m = j;
                float sm = s_id[j], lm = l_id[j];
                float ds = -fmaf(phi, h_sh[m], dz[m]);
                float rc = fmaf(sm, lm, -smu);
                float ivs = frcp(sm);
                float dlam = -fmaf(lm, ds, rc)*ivs;
                float sn = fmaf(alpha, ds, sm);
                float ln = fmaf(alpha, dlam, lm);
                s_id[j] = sn; l_id[j] = ln;
                msn = fmaf(sn, ln, msn);
            }
        } else {
            #pragma unroll
            for (int j = 0; j < 5; j++){
                const int m = 5 + j;
                float sm = s_id[j], lm = l_id[j];
                float ds = -fmaf(phi, h_sh[m], dz[m]);
                float rc = fmaf(sm, lm, -smu);
                float ivs = frcp(sm);
                float dlam = -fmaf(lm, ds, rc)*ivs;
                float sn = fmaf(alpha, ds, sm);
                float ln = fmaf(alpha, dlam, lm);
                s_id[j] = sn; l_id[j] = ln;
                msn = fmaf(sn, ln, msn);
            }
        }
        passB2_blk<2>(saB[0], smu, alpha, msn, sl_sh, r_sh);
        passB2_blk<4>(saB[1], smu, alpha, msn, sl_sh, r_sh);
        passB2_blk<6>(saB[2], smu, alpha, msn, sl_sh, r_sh);
        passB2_blk<8>(saB[3], smu, alpha, msn, sl_sh, r_sh);
        msn += __shfl_xor_sync(0xffffffffu, msn, 1);
        musum = msn;

        phi *= (1.f - alpha);              // rp recurrence
        u64 al2 = pk(alpha, alpha);
        #pragma unroll
        for (int j = 0; j < 5; j++) z2[j] = fma2(al2, dz2[j], z2[j]);
    }
    if (r == 0){
        float z0, z1; upk(z2[0], z0, z1);
        out[item] = z0;
    }
}

// ---------------- launch (4 launches; ipm at index 3 for ncu capture) ----------------
extern "C" void kernel_launch(void* const* d_in, const int* in_sizes, int n_in,
                              void* d_out, int out_size)
{
    (void)in_sizes; (void)n_in; (void)out_size;
    const float* x    = (const float*)d_in[0];
    const float* w1   = (const float*)d_in[1];
    const float* b1   = (const float*)d_in[2];
    const float* w2   = (const float*)d_in[3];
    const float* b2   = (const float*)d_in[4];
    const float* bn1g = (const float*)d_in[5];
    const float* bn1b = (const float*)d_in[6];
    const float* bn2g = (const float*)d_in[7];
    const float* bn2b = (const float*)d_in[8];
    const float* L    = (const float*)d_in[9];
    const float* LP   = (const float*)d_in[10];
    const float* LR   = (const float*)d_in[11];
    const float* A    = (const float*)d_in[12];
    const float* Bm   = (const float*)d_in[13];
    const float* u0   = (const float*)d_in[14];
    const float* s0   = (const float*)d_in[15];
    float* out = (float*)d_out;

    const int ipm_smem = IPB*SROW*(8 + 4);            // u64 sl + float ds = 24,768 B
    cudaFuncSetAttribute(ipm_kernel, cudaFuncAttributeMaxDynamicSharedMemorySize, ipm_smem);

    fc1qp_kernel<<<129, 256>>>(x, w1, b1, L, LP, LR, A, Bm, u0, s0);  // 0
    fold_all<<<NU, 256>>>(w2, b2, bn1g, bn1b);                        // 1
    fc2_kernel<<<NB/32, 256>>>();                                     // 2
    ipm_kernel<<<NB/IPB, 32, ipm_smem>>>(out, bn2g, bn2b);            // 3
}

// round 14
// speedup vs baseline: 1.0395x; 1.0395x over previous
#include <cuda_runtime.h>

#define NB   16384
#define NH   1024
#define NIN  32
#define NU   10
#define MI   138
#define ITER 30
#define SIGMA 0.1f
#define FC1_BLOCKS 128
#define FC2_BLOCKS (NB/32)    // 512

#define IPB  16               // items per IPM block (32 threads, 2 per item)
#define SROW 129              // odd stride -> conflict-free pair access

typedef unsigned long long u64;

// ---------------- device scratch (static, no allocs) ----------------
__device__ float g_h1[NB*NH];              // 64 MB, row-major [item][feature]
__device__ float g_bn1p[FC1_BLOCKS*NH];
__device__ float g_bn1q[FC1_BLOCKS*NH];
__device__ float g_W2f[NU*NH];
__device__ float g_b2f[NU];
__device__ float g_t2[NB*NU];
__device__ float g_bn2p[FC2_BLOCKS*NU];
__device__ float g_bn2q[FC2_BLOCKS*NU];
__device__ float g_Qhat[NU*NU];
__device__ float g_G[MI*NU];
__device__ float g_h[MI];

__device__ __forceinline__ float frcp(float x){ float r; asm("rcp.approx.f32 %0, %1;" : "=f"(r) : "f"(x)); return r; }
__device__ __forceinline__ float lrelu(float v){ return v > 0.f ? v : 0.2f*v; }

// ---- packed f32x2 helpers ----
__device__ __forceinline__ u64 pk(float x, float y){
    u64 r; asm("mov.b64 %0, {%1,%2};" : "=l"(r) : "f"(x), "f"(y)); return r;
}
__device__ __forceinline__ void upk(u64 v, float& x, float& y){
    asm("mov.b64 {%0,%1}, %2;" : "=f"(x), "=f"(y) : "l"(v));
}
__device__ __forceinline__ u64 fma2(u64 a, u64 b, u64 c){
    u64 d; asm("fma.rn.f32x2 %0, %1, %2, %3;" : "=l"(d) : "l"(a), "l"(b), "l"(c)); return d;
}
__device__ __forceinline__ u64 mul2(u64 a, u64 b){
    u64 d; asm("mul.rn.f32x2 %0, %1, %2;" : "=l"(d) : "l"(a), "l"(b)); return d;
}
__device__ __forceinline__ u64 add2(u64 a, u64 b){
    u64 d; asm("add.rn.f32x2 %0, %1, %2;" : "=l"(d) : "l"(a), "l"(b)); return d;
}
__device__ __forceinline__ u64 sh64(u64 v){
    return __shfl_xor_sync(0xffffffffu, v, 1);
}

// ---------------- K0: fc1 (blocks 0..127) + build_qp (block 128) ----------------
__global__ void __launch_bounds__(256) fc1qp_kernel(
    const float* __restrict__ x,  const float* __restrict__ W1, const float* __restrict__ b1,
    const float* __restrict__ L,  const float* __restrict__ LP, const float* __restrict__ LR,
    const float* __restrict__ A,  const float* __restrict__ Bm,
    const float* __restrict__ u0, const float* __restrict__ s0)
{
    __shared__ __align__(16) float sh[5120];
    const int t = threadIdx.x;

    if (blockIdx.x < 128){
        // ================= fc1 =================
        float* xs = sh;
        const int row0 = blockIdx.x * 128;
        {
            const float4* src = (const float4*)(x + row0*32);
            float4* dst = (float4*)xs;
            for (int e = t; e < 1024; e += 256) dst[e] = src[e];
        }
        __syncthreads();
        #pragma unroll
        for (int ff = 0; ff < 4; ff++){
            const int f = t + ff*256;
            float w[32];
            const float4* wp = (const float4*)(W1 + f*32);
            #pragma unroll
            for (int k = 0; k < 8; k++){
                float4 v = wp[k];
                w[4*k+0]=v.x; w[4*k+1]=v.y; w[4*k+2]=v.z; w[4*k+3]=v.w;
            }
            const float bias = b1[f];
            float sum = 0.f, sq = 0.f;
            for (int r = 0; r < 128; r++){
                float acc = bias;
                const float4* xp = (const float4*)(xs + r*32);
                #pragma unroll
                for (int k = 0; k < 8; k++){
                    float4 xv = xp[k];
                    acc = fmaf(xv.x, w[4*k+0], acc);
                    acc = fmaf(xv.y, w[4*k+1], acc);
                    acc = fmaf(xv.z, w[4*k+2], acc);
                    acc = fmaf(xv.w, w[4*k+3], acc);
                }
                float v = lrelu(acc);
                g_h1[(row0+r)*NH + f] = v;
                sum += v; sq = fmaf(v, v, sq);
            }
            g_bn1p[blockIdx.x*NH + f] = sum;
            g_bn1q[blockIdx.x*NH + f] = sq;
        }
        return;
    }

    // ================= build_qp (block 128) =================
    float* Q  = sh;            // 1024
    float* P  = sh + 1024;     // 1024
    float* Bh = sh + 2048;     // 1280
    float* Ms = sh + 3328;     // 1280
    float* pw = sh + 4608;     // 256 (4 x 64)
    float* R  = sh + 4864;     // 4

    for (int e = t; e < 1024; e += 256){
        int i = e >> 5, j = e & 31;
        int kmax = i < j ? i : j;
        float aq = (i==j) ? 1e-4f : 0.f;
        float ap = aq;
        for (int k = 0; k <= kmax; k++){
            aq = fmaf(L [i*32+k], L [j*32+k], aq);
            ap = fmaf(LP[i*32+k], LP[j*32+k], ap);
        }
        Q[e] = aq; P[e] = ap;
    }
    if (t < 4){
        int i = t >> 1, j = t & 1;
        int kmax = i < j ? i : j;
        float a = (i==j) ? 1e-4f : 0.f;
        for (int k = 0; k <= kmax; k++) a = fmaf(LR[i*2+k], LR[j*2+k], a);
        R[t] = a;
    }
    if (t < 64) pw[t] = Bm[t];
    __syncthreads();
    for (int s = 1; s < 4; s++){
        if (t < 64){
            int r = t >> 1, c = t & 1;
            float acc = 0.f;
            for (int k = 0; k < 32; k++) acc = fmaf(A[r*32+k], pw[(s-1)*64 + k*2+c], acc);
            pw[s*64 + t] = acc;
        }
        __syncthreads();
    }
    for (int e = t; e < 128*NU; e += 256){
        int row = e / NU, col = e - row*NU;
        int bi = row >> 5, r = row & 31, bj = col >> 1, c = col & 1;
        Bh[e] = (bj <= bi) ? pw[(bi-bj)*64 + r*2+c] : 0.f;
    }
    __syncthreads();
    for (int e = t; e < 128*NU; e += 256){
        int row = e / NU, col = e - row*NU;
        int b = row >> 5, r = row & 31;
        const float* Qb = (b < 3) ? Q : P;
        float acc = 0.f;
        for (int k = 0; k < 32; k++) acc = fmaf(Qb[r*32+k], Bh[(b*32+k)*NU+col], acc);
        Ms[e] = acc;
    }
    __syncthreads();
    if (t < 100){
        int a = t / NU, b = t - (t/NU)*NU;
        float acc = ((a>>1) == (b>>1)) ? R[(a&1)*2+(b&1)] : 0.f;
        for (int row = 0; row < 128; row++) acc = fmaf(Bh[row*NU+a], Ms[row*NU+b], acc);
        g_Qhat[t] = acc;
    }
    for (int e = t; e < MI*NU; e += 256){
        int row = e / NU, col = e - (e/NU)*NU;
        g_G[e] = (row < NU) ? ((row==col) ? 1.f : 0.f) : Bh[(row-NU)*NU+col];
    }
    if (t < MI){
        float acc = s0[t];
        if (t < NU) acc += u0[t];
        else { for (int j = 0; j < NU; j++) acc = fmaf(Bh[(t-NU)*NU+j], u0[j], acc); }
        g_h[t] = acc;
    }
}

// ---------------- K1: bn1 finalize fused with fc2-weight fold ----------------
__global__ void fold_all(const float* __restrict__ W2, const float* __restrict__ b2,
                         const float* __restrict__ g1, const float* __restrict__ beta1)
{
    __shared__ float red[256];
    const int u = blockIdx.x, t = threadIdx.x;
    float dot = 0.f;
    for (int k = t; k < NH; k += 256){
        float sum = 0.f, sq = 0.f;
        for (int b = 0; b < FC1_BLOCKS; b++){
            sum += g_bn1p[b*NH + k];
            sq  += g_bn1q[b*NH + k];
        }
        float mu  = sum * (1.f/(float)NB);
        float var = sq  * (1.f/(float)NB) - mu*mu;
        float a = g1[k]*rsqrtf(var + 1e-5f);
        float c = beta1[k] - mu*a;
        float wv = W2[u*NH + k];
        g_W2f[u*NH + k] = wv * a;
        dot = fmaf(wv, c, dot);
    }
    red[t] = dot; __syncthreads();
    for (int s = 128; s > 0; s >>= 1){
        if (t < s) red[t] += red[t+s];
        __syncthreads();
    }
    if (t == 0) g_b2f[u] = b2[u] + red[0];
}

// ---------------- K2: fc2 (4 items per warp) + leaky_relu + bn2 stats ----------------
__global__ void __launch_bounds__(256) fc2_kernel()
{
    __shared__ float Ws[NU*NH];
    __shared__ float bs[NU];
    __shared__ float wt2[32][NU];
    const int t = threadIdx.x, lane = t & 31, wid = t >> 5;
    for (int e = t; e < NU*NH; e += 256) Ws[e] = g_W2f[e];
    if (t < NU) bs[t] = g_b2f[t];
    __syncthreads();
    const int item0 = blockIdx.x*32 + wid*4;
    float acc0[NU], acc1[NU], acc2[NU], acc3[NU];
    #pragma unroll
    for (int u = 0; u < NU; u++){ acc0[u]=0.f; acc1[u]=0.f; acc2[u]=0.f; acc3[u]=0.f; }
    const float* h0 = g_h1 + item0*NH;
    const float* h1r = h0 + NH;
    const float* h2r = h0 + 2*NH;
    const float* h3r = h0 + 3*NH;
    for (int j = 0; j < 32; j++){
        float v0 = h0[j*32 + lane];
        float v1 = h1r[j*32 + lane];
        float v2 = h2r[j*32 + lane];
        float v3 = h3r[j*32 + lane];
        #pragma unroll
        for (int u = 0; u < NU; u++){
            float wv = Ws[u*NH + j*32 + lane];
            acc0[u] = fmaf(v0, wv, acc0[u]);
            acc1[u] = fmaf(v1, wv, acc1[u]);
            acc2[u] = fmaf(v2, wv, acc2[u]);
            acc3[u] = fmaf(v3, wv, acc3[u]);
        }
    }
    #pragma unroll
    for (int u = 0; u < NU; u++){
        #pragma unroll
        for (int off = 16; off > 0; off >>= 1){
            acc0[u] += __shfl_xor_sync(0xffffffffu, acc0[u], off);
            acc1[u] += __shfl_xor_sync(0xffffffffu, acc1[u], off);
            acc2[u] += __shfl_xor_sync(0xffffffffu, acc2[u], off);
            acc3[u] += __shfl_xor_sync(0xffffffffu, acc3[u], off);
        }
    }
    if (lane == 0){
        #pragma unroll
        for (int u = 0; u < NU; u++){
            float v0 = lrelu(acc0[u] + bs[u]);
            float v1 = lrelu(acc1[u] + bs[u]);
            float v2 = lrelu(acc2[u] + bs[u]);
            float v3 = lrelu(acc3[u] + bs[u]);
            g_t2[(item0+0)*NU + u] = v0;
            g_t2[(item0+1)*NU + u] = v1;
            g_t2[(item0+2)*NU + u] = v2;
            g_t2[(item0+3)*NU + u] = v3;
            wt2[wid*4+0][u] = v0;
            wt2[wid*4+1][u] = v1;
            wt2[wid*4+2][u] = v2;
            wt2[wid*4+3][u] = v3;
        }
    }
    __syncthreads();
    if (t < NU){
        float s = 0.f, q = 0.f;
        #pragma unroll
        for (int w = 0; w < 32; w++){ float v = wt2[w][t]; s += v; q = fmaf(v, v, q); }
        g_bn2p[blockIdx.x*NU + t] = s;
        g_bn2q[blockIdx.x*NU + t] = q;
    }
}

// ---------------- K3: batched IPM, 32-thread blocks (16 items), rp-recurrence ----------------
#define HOFF0 0
#define HOFF1 1
#define HOFF2 2
#define HOFF3 4
#define HOFF4 6
#define HOFF5 9
#define HOFF6 12
#define HOFF7 16
#define HOFF8 20
#define HOFF9 25

template<int K>
__device__ __forceinline__ void passA_blk(const float* __restrict__ Gblk, int sa0, int hBase,
    float phi, u64* H2, u64* b1p, float smu,
    const float* s_sh, const float* l_sh, const float* h_sh)
{
    const int HOFF[10] = {HOFF0,HOFF1,HOFF2,HOFF3,HOFF4,HOFF5,HOFF6,HOFF7,HOFF8,HOFF9};
    const int KH = K/2;
    #pragma unroll 4
    for (int j = 0; j < 16; j++){
        const int sa = sa0 + j;
        float sm = s_sh[sa], lm = l_sh[sa];
        float ivs = frcp(sm);
        float w = lm*ivs;
        float rp = phi * h_sh[hBase + j];          // rp = phi*(1-h)
        float coef = fmaf(lm, rp, smu)*ivs;
        float2 gv[KH]; u64 g2[KH];
        #pragma unroll
        for (int jj = 0; jj < KH; jj++){
            gv[jj] = *(const float2*)&Gblk[j*K + 2*jj];
            g2[jj] = pk(gv[jj].x, gv[jj].y);
        }
        u64 w2v = pk(w, w), c2 = pk(coef, coef);
        u64 wgp[KH];
        #pragma unroll
        for (int jj = 0; jj < KH; jj++){
            wgp[jj] = mul2(w2v, g2[jj]);
            b1p[jj] = fma2(c2, g2[jj], b1p[jj]);
        }
        #pragma unroll
        for (int a = 0; a < K; a++){
            float ga = (a & 1) ? gv[a>>1].y : gv[a>>1].x;
            u64 ga2 = pk(ga, ga);
            #pragma unroll
            for (int pi = 0; pi <= (a>>1); pi++)
                H2[HOFF[a]+pi] = fma2(ga2, wgp[pi], H2[HOFF[a]+pi]);
        }
    }
}

template<int K>
__device__ __forceinline__ void passB1_blk(const float* __restrict__ Gblk, int sa0, int hBase,
    const u64* dz2, float phi, float smu, float& q,
    const float* s_sh, const float* l_sh, float* r_sh, const float* h_sh)
{
    const int KH = K/2;
    #pragma unroll 4
    for (int j = 0; j < 16; j++){
        const int sa = sa0 + j;
        float sm = s_sh[sa], lm = l_sh[sa];
        u64 acc = pk(0.f, 0.f);
        #pragma unroll
        for (int jj = 0; jj < KH; jj++){
            float2 gvj = *(const float2*)&Gblk[j*K + 2*jj];
            acc = fma2(pk(gvj.x, gvj.y), dz2[jj], acc);
        }
        float gx, gy; upk(acc, gx, gy);
        float ds = -fmaf(phi, h_sh[hBase + j], gx + gy);   // alpha-independent
        r_sh[sa] = ds;
        float ivsl = frcp(sm*lm);
        float r1 = -ds*lm*ivsl;
        float r2 = fmaf(fmaf(ds, lm, -smu), ivsl, 1.f);
        q = fmaxf(q, fmaxf(r1, r2));
    }
}

template<int K>
__device__ __forceinline__ void passB2_blk(int sa0,
    float smu, float alpha, float& msn,
    float* s_sh, float* l_sh, const float* r_sh)
{
    #pragma unroll 4
    for (int j = 0; j < 16; j++){
        const int sa = sa0 + j;
        float sm = s_sh[sa], lm = l_sh[sa];
        float ds = r_sh[sa];
        float rc = fmaf(sm, lm, -smu);
        float ivs = frcp(sm);
        float dlam = -fmaf(lm, ds, rc)*ivs;
        float sn = fmaf(alpha, ds, sm);
        float ln = fmaf(alpha, dlam, lm);
        s_sh[sa] = sn; l_sh[sa] = ln;
        msn = fmaf(sn, ln, msn);
    }
}

__global__ void __launch_bounds__(32, 7) ipm_kernel(float* __restrict__ out,
    const float* __restrict__ g2, const float* __restrict__ beta2)
{
    extern __shared__ float dyn[];
    float* s_sh = dyn;                    // IPB*SROW
    float* l_sh = dyn +   IPB*SROW;
    float* r_sh = dyn + 2*IPB*SROW;       // ds cache
    __shared__ __align__(8) float G_sh[704];
    __shared__ float h_sh[MI];            // holds (1 - h)
    __shared__ __align__(8) float Q_sh[NU*NU];
    __shared__ float ac_sh[2*NU];
    const int GA[4] = {0, 80, 224, 432};
    const int GB[4] = {48, 160, 336, 576};

    const int tid = threadIdx.x;          // 0..31 (one warp)
    const int r = tid & 1, q = tid >> 1;  // q in 0..15
    const int item = blockIdx.x*IPB + q;

    // ---- preamble: bn2 finalize (redundant per block; warp-shuffle reduce)
    {
        float loc[20];
        #pragma unroll
        for (int j = 0; j < 20; j++) loc[j] = 0.f;
        for (int b = tid; b < FC2_BLOCKS; b += 32){
            #pragma unroll
            for (int u = 0; u < NU; u++){
                loc[u]    += g_bn2p[b*NU + u];
                loc[10+u] += g_bn2q[b*NU + u];
            }
        }
        #pragma unroll
        for (int j = 0; j < 20; j++){
            #pragma unroll
            for (int off = 16; off > 0; off >>= 1)
                loc[j] += __shfl_xor_sync(0xffffffffu, loc[j], off);
        }
        if (tid < NU){
            float sv = 0.f, qv = 0.f;
            #pragma unroll
            for (int u = 0; u < NU; u++){
                if (tid == u){ sv = loc[u]; qv = loc[10+u]; }
            }
            float mu  = sv * (1.f/(float)NB);
            float var = qv * (1.f/(float)NB) - mu*mu;
            float a = g2[tid]*rsqrtf(var + 1e-5f);
            ac_sh[tid]      = a;
            ac_sh[NU + tid] = beta2[tid] - mu*a;
        }
    }

    // loads (32 threads)
    for (int mm = tid; mm < 128; mm += 32){
        int bi = mm >> 5, lr = mm & 31, hf = lr >> 4, j = lr & 15, K = 2*bi + 2;
        int base = (hf ? GB[bi] : GA[bi]) + j*K;
        for (int c = 0; c < K; c++) G_sh[base + c] = g_G[(10+mm)*NU + c];
    }
    for (int i = tid; i < MI; i += 32) h_sh[i] = 1.f - g_h[i];   // (1-h)
    for (int i = tid; i < 100; i += 32) Q_sh[i] = g_Qhat[i];
    __syncthreads();

    float p[NU];
    u64 z2[5];
    #pragma unroll
    for (int u = 0; u < NU; u++)
        p[u] = fmaf(g_t2[item*NU+u], ac_sh[u], ac_sh[NU+u]);
    #pragma unroll
    for (int j = 0; j < 5; j++) z2[j] = pk(0.f, 0.f);

    float s_id[5], l_id[5];
    #pragma unroll
    for (int j = 0; j < 5; j++){ s_id[j] = 1.f; l_id[j] = 1.f; }

    int saB[4], hB[4];
    const float* Gb[4];
    #pragma unroll
    for (int bi = 0; bi < 4; bi++){
        int mm0 = 32*bi + 16*r;
        saB[bi] = q*SROW + mm0;
        hB[bi]  = 10 + mm0;
        Gb[bi]  = &G_sh[r ? GB[bi] : GA[bi]];
        #pragma unroll 4
        for (int j = 0; j < 16; j++){
            s_sh[saB[bi]+j] = 1.f; l_sh[saB[bi]+j] = 1.f;
        }
    }
    float musum = (float)MI;
    float phi = 1.f;                       // prod(1-alpha)

    for (int it = 0; it < ITER; it++){
        float smu = musum * (SIGMA/(float)MI);
        u64 H2[30], b1p[5];
        #pragma unroll
        for (int e = 0; e < 30; e++) H2[e] = pk(0.f, 0.f);
        #pragma unroll
        for (int j = 0; j < 5; j++) b1p[j] = pk(0.f, 0.f);

        // identity rows: compile-time indices per parity branch
        if (r == 0){
            #pragma unroll
            for (int j = 0; j < 5; j++){
                const int m = j;
                float sm = s_id[j], lm = l_id[j];
                float ivs = frcp(sm);
                float w = lm*ivs;
                float rp = phi * h_sh[m];
                float c = fmaf(lm, rp, smu)*ivs;
                b1p[m/2] = add2(b1p[m/2], (m&1) ? pk(0.f,c) : pk(c,0.f));
                const int ho = (m==0?HOFF0:m==1?HOFF1:m==2?HOFF2:m==3?HOFF3:HOFF4) + m/2;
                H2[ho] = add2(H2[ho], (m&1) ? pk(0.f,w) : pk(w,0.f));
            }
        } else {
            #pragma unroll
            for (int j = 0; j < 5; j++){
                const int m = 5 + j;
                float sm = s_id[j], lm = l_id[j];
                float ivs = frcp(sm);
                float w = lm*ivs;
                float rp = phi * h_sh[m];
                float c = fmaf(lm, rp, smu)*ivs;
                b1p[m/2] = add2(b1p[m/2], (m&1) ? pk(0.f,c) : pk(c,0.f));
                const int ho = (m==5?HOFF5:m==6?HOFF6:m==7?HOFF7:m==8?HOFF8:HOFF9) + m/2;
                H2[ho] = add2(H2[ho], (m&1) ? pk(0.f,w) : pk(w,0.f));
            }
        }

        passA_blk<2>(Gb[0], saB[0], hB[0], phi, H2, b1p, smu, s_sh, l_sh, h_sh);
        passA_blk<4>(Gb[1], saB[1], hB[1], phi, H2, b1p, smu, s_sh, l_sh, h_sh);
        passA_blk<6>(Gb[2], saB[2], hB[2], phi, H2, b1p, smu, s_sh, l_sh, h_sh);
        passA_blk<8>(Gb[3], saB[3], hB[3], phi, H2, b1p, smu, s_sh, l_sh, h_sh);

        #pragma unroll
        for (int e = 0; e < 30; e++) H2[e] = add2(H2[e], sh64(H2[e]));
        #pragma unroll
        for (int j = 0; j < 5; j++) b1p[j] = add2(b1p[j], sh64(b1p[j]));

        const int HOFF[10] = {HOFF0,HOFF1,HOFF2,HOFF3,HOFF4,HOFF5,HOFF6,HOFF7,HOFF8,HOFF9};
        float Hs[55];
        #pragma unroll
        for (int a = 0; a < NU; a++){
            #pragma unroll
            for (int pi = 0; pi <= (a>>1); pi++){
                float x, y; upk(H2[HOFF[a]+pi], x, y);
                Hs[(a*(a+1))/2 + 2*pi] = x + Q_sh[a*NU + 2*pi];
                if (2*pi+1 <= a) Hs[(a*(a+1))/2 + 2*pi+1] = y + Q_sh[a*NU + 2*pi+1];
            }
        }
        float b1[NU];
        #pragma unroll
        for (int j = 0; j < 5; j++) upk(b1p[j], b1[2*j], b1[2*j+1]);

        float dz[NU];
        #pragma unroll
        for (int i = 0; i < NU; i++){
            u64 acc = pk(0.f, 0.f);
            #pragma unroll
            for (int j = 0; j < 5; j++){
                float2 qv = *(const float2*)&Q_sh[i*NU + 2*j];
                acc = fma2(pk(qv.x, qv.y), z2[j], acc);
            }
            float qx, qy; upk(acc, qx, qy);
            dz[i] = -(p[i] + b1[i] + qx + qy);
        }
        #pragma unroll
        for (int k = 0; k < NU; k++){
            float inv = rsqrtf(Hs[(k*(k+1))/2+k]);
            Hs[(k*(k+1))/2+k] = inv;
            #pragma unroll
            for (int i = k+1; i < NU; i++) Hs[(i*(i+1))/2+k] *= inv;
            #pragma unroll
            for (int j = k+1; j < NU; j++){
                float ljk = Hs[(j*(j+1))/2+k];
                #pragma unroll
                for (int i = j; i < NU; i++)
                    Hs[(i*(i+1))/2+j] = fmaf(-Hs[(i*(i+1))/2+k], ljk, Hs[(i*(i+1))/2+j]);
            }
        }
        #pragma unroll
        for (int i = 0; i < NU; i++){
            float tt = dz[i];
            #pragma unroll
            for (int j = 0; j < i; j++) tt = fmaf(-Hs[(i*(i+1))/2+j], dz[j], tt);
            dz[i] = tt * Hs[(i*(i+1))/2+i];
        }
        #pragma unroll
        for (int i = NU-1; i >= 0; i--){
            float tt = dz[i];
            #pragma unroll
            for (int j = i+1; j < NU; j++) tt = fmaf(-Hs[(j*(j+1))/2+i], dz[j], tt);
            dz[i] = tt * Hs[(i*(i+1))/2+i];
        }
        u64 dz2[5];
        #pragma unroll
        for (int j = 0; j < 5; j++) dz2[j] = pk(dz[2*j], dz[2*j+1]);

        // ---- pass B1: ds cached in r_sh; step-length ratios ----
        float qm = 0.f;
        if (r == 0){
            #pragma unroll
            for (int j = 0; j < 5; j++){
                const int m = j;
                float sm = s_id[j], lm = l_id[j];
                float ds = -fmaf(phi, h_sh[m], dz[m]);
                float ivsl = frcp(sm*lm);
                float r1 = -ds*lm*ivsl;
                float r2 = fmaf(fmaf(ds, lm, -smu), ivsl, 1.f);
                qm = fmaxf(qm, fmaxf(r1, r2));
            }
        } else {
            #pragma unroll
            for (int j = 0; j < 5; j++){
                const int m = 5 + j;
                float sm = s_id[j], lm = l_id[j];
                float ds = -fmaf(phi, h_sh[m], dz[m]);
                float ivsl = frcp(sm*lm);
                float r1 = -ds*lm*ivsl;
                float r2 = fmaf(fmaf(ds, lm, -smu), ivsl, 1.f);
                qm = fmaxf(qm, fmaxf(r1, r2));
            }
        }
        passB1_blk<2>(Gb[0], saB[0], hB[0], dz2, phi, smu, qm, s_sh, l_sh, r_sh, h_sh);
        passB1_blk<4>(Gb[1], saB[1], hB[1], dz2, phi, smu, qm, s_sh, l_sh, r_sh, h_sh);
        passB1_blk<6>(Gb[2], saB[2], hB[2], dz2, phi, smu, qm, s_sh, l_sh, r_sh, h_sh);
        passB1_blk<8>(Gb[3], saB[3], hB[3], dz2, phi, smu, qm, s_sh, l_sh, r_sh, h_sh);
        qm = fmaxf(qm, __shfl_xor_sync(0xffffffffu, qm, 1));
        float alpha = fminf(1.f, 0.99f*frcp(qm));

        // ---- pass B2: ds from r_sh; update s/lam; accumulate musum ----
        float msn = 0.f;
        if (r == 0){
            #pragma unroll
            for (int j = 0; j < 5; j++){
                const int m = j;
                float sm = s_id[j], lm = l_id[j];
                float ds = -fmaf(phi, h_sh[m], dz[m]);
                float rc = fmaf(sm, lm, -smu);
                float ivs = frcp(sm);
                float dlam = -fmaf(lm, ds, rc)*ivs;
                float sn = fmaf(alpha, ds, sm);
                float ln = fmaf(alpha, dlam, lm);
                s_id[j] = sn; l_id[j] = ln;
                msn = fmaf(sn, ln, msn);
            }
        } else {
            #pragma unroll
            for (int j = 0; j < 5; j++){
                const int m = 5 + j;
                float sm = s_id[j], lm = l_id[j];
                float ds = -fmaf(phi, h_sh[m], dz[m]);
                float rc = fmaf(sm, lm, -smu);
                float ivs = frcp(sm);
                float dlam = -fmaf(lm, ds, rc)*ivs;
                float sn = fmaf(alpha, ds, sm);
                float ln = fmaf(alpha, dlam, lm);
                s_id[j] = sn; l_id[j] = ln;
                msn = fmaf(sn, ln, msn);
            }
        }
        passB2_blk<2>(saB[0], smu, alpha, msn, s_sh, l_sh, r_sh);
        passB2_blk<4>(saB[1], smu, alpha, msn, s_sh, l_sh, r_sh);
        passB2_blk<6>(saB[2], smu, alpha, msn, s_sh, l_sh, r_sh);
        passB2_blk<8>(saB[3], smu, alpha, msn, s_sh, l_sh, r_sh);
        msn += __shfl_xor_sync(0xffffffffu, msn, 1);
        musum = msn;

        phi *= (1.f - alpha);              // rp recurrence
        u64 al2 = pk(alpha, alpha);
        #pragma unroll
        for (int j = 0; j < 5; j++) z2[j] = fma2(al2, dz2[j], z2[j]);
    }
    if (r == 0){
        float z0, z1; upk(z2[0], z0, z1);
        out[item] = z0;
    }
}

// ---------------- launch (4 launches; ipm at index 3 for ncu capture) ----------------
extern "C" void kernel_launch(void* const* d_in, const int* in_sizes, int n_in,
                              void* d_out, int out_size)
{
    (void)in_sizes; (void)n_in; (void)out_size;
    const float* x    = (const float*)d_in[0];
    const float* w1   = (const float*)d_in[1];
    const float* b1   = (const float*)d_in[2];
    const float* w2   = (const float*)d_in[3];
    const float* b2   = (const float*)d_in[4];
    const float* bn1g = (const float*)d_in[5];
    const float* bn1b = (const float*)d_in[6];
    const float* bn2g = (const float*)d_in[7];
    const float* bn2b = (const float*)d_in[8];
    const float* L    = (const float*)d_in[9];
    const float* LP   = (const float*)d_in[10];
    const float* LR   = (const float*)d_in[11];
    const float* A    = (const float*)d_in[12];
    const float* Bm   = (const float*)d_in[13];
    const float* u0   = (const float*)d_in[14];
    const float* s0   = (const float*)d_in[15];
    float* out = (float*)d_out;

    const int ipm_smem = 3*IPB*SROW*(int)sizeof(float);   // 24,768 B
    cudaFuncSetAttribute(ipm_kernel, cudaFuncAttributeMaxDynamicSharedMemorySize, ipm_smem);

    fc1qp_kernel<<<129, 256>>>(x, w1, b1, L, LP, LR, A, Bm, u0, s0);  // 0
    fold_all<<<NU, 256>>>(w2, b2, bn1g, bn1b);                        // 1
    fc2_kernel<<<NB/32, 256>>>();                                     // 2
    ipm_kernel<<<NB/IPB, 32, ipm_smem>>>(out, bn2g, bn2b);            // 3
}

// round 15
// speedup vs baseline: 1.0608x; 1.0205x over previous
#include <cuda_runtime.h>

#define NB   16384
#define NH   1024
#define NIN  32
#define NU   10
#define MI   138
#define ITER 30
#define SIGMA 0.1f
#define FC1_BLOCKS 128
#define FC2_BLOCKS (NB/32)    // 512

#define IPB  16               // items per IPM block (32 threads, 2 per item)
#define SROW 129              // odd stride -> conflict-free pair access

typedef unsigned long long u64;

// ---------------- device scratch (static, no allocs) ----------------
__device__ float g_h1[NB*NH];              // 64 MB, row-major [item][feature]
__device__ float g_bn1p[FC1_BLOCKS*NH];
__device__ float g_bn1q[FC1_BLOCKS*NH];
__device__ float g_W2f[NU*NH];
__device__ float g_b2f[NU];
__device__ float g_t2[NB*NU];
__device__ float g_bn2p[FC2_BLOCKS*NU];
__device__ float g_bn2q[FC2_BLOCKS*NU];
__device__ float g_Qhat[NU*NU];
__device__ float g_G[MI*NU];
__device__ float g_h[MI];

__device__ __forceinline__ float frcp(float x){ float r; asm("rcp.approx.f32 %0, %1;" : "=f"(r) : "f"(x)); return r; }
__device__ __forceinline__ float lrelu(float v){ return v > 0.f ? v : 0.2f*v; }

// ---- packed f32x2 helpers ----
__device__ __forceinline__ u64 pk(float x, float y){
    u64 r; asm("mov.b64 %0, {%1,%2};" : "=l"(r) : "f"(x), "f"(y)); return r;
}
__device__ __forceinline__ void upk(u64 v, float& x, float& y){
    asm("mov.b64 {%0,%1}, %2;" : "=f"(x), "=f"(y) : "l"(v));
}
__device__ __forceinline__ u64 fma2(u64 a, u64 b, u64 c){
    u64 d; asm("fma.rn.f32x2 %0, %1, %2, %3;" : "=l"(d) : "l"(a), "l"(b), "l"(c)); return d;
}
__device__ __forceinline__ u64 mul2(u64 a, u64 b){
    u64 d; asm("mul.rn.f32x2 %0, %1, %2;" : "=l"(d) : "l"(a), "l"(b)); return d;
}
__device__ __forceinline__ u64 add2(u64 a, u64 b){
    u64 d; asm("add.rn.f32x2 %0, %1, %2;" : "=l"(d) : "l"(a), "l"(b)); return d;
}
__device__ __forceinline__ u64 sh64(u64 v){
    return __shfl_xor_sync(0xffffffffu, v, 1);
}

// ---------------- K0: fc1 (blocks 0..127, f32x2 inner) + build_qp (block 128) ----------------
__global__ void __launch_bounds__(256) fc1qp_kernel(
    const float* __restrict__ x,  const float* __restrict__ W1, const float* __restrict__ b1,
    const float* __restrict__ L,  const float* __restrict__ LP, const float* __restrict__ LR,
    const float* __restrict__ A,  const float* __restrict__ Bm,
    const float* __restrict__ u0, const float* __restrict__ s0)
{
    __shared__ __align__(16) float sh[5120];
    const int t = threadIdx.x;

    if (blockIdx.x < 128){
        // ================= fc1 (f32x2 packed dot) =================
        float* xs = sh;
        const int row0 = blockIdx.x * 128;
        {
            const float4* src = (const float4*)(x + row0*32);
            float4* dst = (float4*)xs;
            for (int e = t; e < 1024; e += 256) dst[e] = src[e];
        }
        __syncthreads();
        #pragma unroll
        for (int ff = 0; ff < 4; ff++){
            const int f = t + ff*256;
            u64 w2[16];
            const float4* wp = (const float4*)(W1 + f*32);
            #pragma unroll
            for (int k = 0; k < 8; k++){
                float4 v = wp[k];
                w2[2*k+0] = pk(v.x, v.y);
                w2[2*k+1] = pk(v.z, v.w);
            }
            const float bias = b1[f];
            float sum = 0.f, sq = 0.f;
            for (int r = 0; r < 128; r++){
                const ulonglong2* xp = (const ulonglong2*)(xs + r*32);
                u64 accA = pk(bias, 0.f), accB = pk(0.f, 0.f);
                #pragma unroll
                for (int kk = 0; kk < 8; kk++){
                    ulonglong2 xv = xp[kk];
                    accA = fma2(w2[2*kk+0], xv.x, accA);
                    accB = fma2(w2[2*kk+1], xv.y, accB);
                }
                float a0, a1v; upk(add2(accA, accB), a0, a1v);
                float v = lrelu(a0 + a1v);
                g_h1[(row0+r)*NH + f] = v;
                sum += v; sq = fmaf(v, v, sq);
            }
            g_bn1p[blockIdx.x*NH + f] = sum;
            g_bn1q[blockIdx.x*NH + f] = sq;
        }
        return;
    }

    // ================= build_qp (block 128) =================
    float* Q  = sh;            // 1024
    float* P  = sh + 1024;     // 1024
    float* Bh = sh + 2048;     // 1280
    float* Ms = sh + 3328;     // 1280
    float* pw = sh + 4608;     // 256 (4 x 64)
    float* R  = sh + 4864;     // 4

    for (int e = t; e < 1024; e += 256){
        int i = e >> 5, j = e & 31;
        int kmax = i < j ? i : j;
        float aq = (i==j) ? 1e-4f : 0.f;
        float ap = aq;
        for (int k = 0; k <= kmax; k++){
            aq = fmaf(L [i*32+k], L [j*32+k], aq);
            ap = fmaf(LP[i*32+k], LP[j*32+k], ap);
        }
        Q[e] = aq; P[e] = ap;
    }
    if (t < 4){
        int i = t >> 1, j = t & 1;
        int kmax = i < j ? i : j;
        float a = (i==j) ? 1e-4f : 0.f;
        for (int k = 0; k <= kmax; k++) a = fmaf(LR[i*2+k], LR[j*2+k], a);
        R[t] = a;
    }
    if (t < 64) pw[t] = Bm[t];
    __syncthreads();
    for (int s = 1; s < 4; s++){
        if (t < 64){
            int r = t >> 1, c = t & 1;
            float acc = 0.f;
            for (int k = 0; k < 32; k++) acc = fmaf(A[r*32+k], pw[(s-1)*64 + k*2+c], acc);
            pw[s*64 + t] = acc;
        }
        __syncthreads();
    }
    for (int e = t; e < 128*NU; e += 256){
        int row = e / NU, col = e - row*NU;
        int bi = row >> 5, r = row & 31, bj = col >> 1, c = col & 1;
        Bh[e] = (bj <= bi) ? pw[(bi-bj)*64 + r*2+c] : 0.f;
    }
    __syncthreads();
    for (int e = t; e < 128*NU; e += 256){
        int row = e / NU, col = e - row*NU;
        int b = row >> 5, r = row & 31;
        const float* Qb = (b < 3) ? Q : P;
        float acc = 0.f;
        for (int k = 0; k < 32; k++) acc = fmaf(Qb[r*32+k], Bh[(b*32+k)*NU+col], acc);
        Ms[e] = acc;
    }
    __syncthreads();
    if (t < 100){
        int a = t / NU, b = t - (t/NU)*NU;
        float acc = ((a>>1) == (b>>1)) ? R[(a&1)*2+(b&1)] : 0.f;
        for (int row = 0; row < 128; row++) acc = fmaf(Bh[row*NU+a], Ms[row*NU+b], acc);
        g_Qhat[t] = acc;
    }
    for (int e = t; e < MI*NU; e += 256){
        int row = e / NU, col = e - (e/NU)*NU;
        g_G[e] = (row < NU) ? ((row==col) ? 1.f : 0.f) : Bh[(row-NU)*NU+col];
    }
    if (t < MI){
        float acc = s0[t];
        if (t < NU) acc += u0[t];
        else { for (int j = 0; j < NU; j++) acc = fmaf(Bh[(t-NU)*NU+j], u0[j], acc); }
        g_h[t] = acc;
    }
}

// ---------------- K1: bn1 finalize fused with fc2-weight fold ----------------
__global__ void fold_all(const float* __restrict__ W2, const float* __restrict__ b2,
                         const float* __restrict__ g1, const float* __restrict__ beta1)
{
    __shared__ float red[256];
    const int u = blockIdx.x, t = threadIdx.x;
    float dot = 0.f;
    for (int k = t; k < NH; k += 256){
        float sum = 0.f, sq = 0.f;
        for (int b = 0; b < FC1_BLOCKS; b++){
            sum += g_bn1p[b*NH + k];
            sq  += g_bn1q[b*NH + k];
        }
        float mu  = sum * (1.f/(float)NB);
        float var = sq  * (1.f/(float)NB) - mu*mu;
        float a = g1[k]*rsqrtf(var + 1e-5f);
        float c = beta1[k] - mu*a;
        float wv = W2[u*NH + k];
        g_W2f[u*NH + k] = wv * a;
        dot = fmaf(wv, c, dot);
    }
    red[t] = dot; __syncthreads();
    for (int s = 128; s > 0; s >>= 1){
        if (t < s) red[t] += red[t+s];
        __syncthreads();
    }
    if (t == 0) g_b2f[u] = b2[u] + red[0];
}

// ---------------- K2: fc2 (4 items per warp) + leaky_relu + bn2 stats ----------------
__global__ void __launch_bounds__(256) fc2_kernel()
{
    __shared__ float Ws[NU*NH];
    __shared__ float bs[NU];
    __shared__ float wt2[32][NU];
    const int t = threadIdx.x, lane = t & 31, wid = t >> 5;
    for (int e = t; e < NU*NH; e += 256) Ws[e] = g_W2f[e];
    if (t < NU) bs[t] = g_b2f[t];
    __syncthreads();
    const int item0 = blockIdx.x*32 + wid*4;
    float acc0[NU], acc1[NU], acc2[NU], acc3[NU];
    #pragma unroll
    for (int u = 0; u < NU; u++){ acc0[u]=0.f; acc1[u]=0.f; acc2[u]=0.f; acc3[u]=0.f; }
    const float* h0 = g_h1 + item0*NH;
    const float* h1r = h0 + NH;
    const float* h2r = h0 + 2*NH;
    const float* h3r = h0 + 3*NH;
    for (int j = 0; j < 32; j++){
        float v0 = h0[j*32 + lane];
        float v1 = h1r[j*32 + lane];
        float v2 = h2r[j*32 + lane];
        float v3 = h3r[j*32 + lane];
        #pragma unroll
        for (int u = 0; u < NU; u++){
            float wv = Ws[u*NH + j*32 + lane];
            acc0[u] = fmaf(v0, wv, acc0[u]);
            acc1[u] = fmaf(v1, wv, acc1[u]);
            acc2[u] = fmaf(v2, wv, acc2[u]);
            acc3[u] = fmaf(v3, wv, acc3[u]);
        }
    }
    #pragma unroll
    for (int u = 0; u < NU; u++){
        #pragma unroll
        for (int off = 16; off > 0; off >>= 1){
            acc0[u] += __shfl_xor_sync(0xffffffffu, acc0[u], off);
            acc1[u] += __shfl_xor_sync(0xffffffffu, acc1[u], off);
            acc2[u] += __shfl_xor_sync(0xffffffffu, acc2[u], off);
            acc3[u] += __shfl_xor_sync(0xffffffffu, acc3[u], off);
        }
    }
    if (lane == 0){
        #pragma unroll
        for (int u = 0; u < NU; u++){
            float v0 = lrelu(acc0[u] + bs[u]);
            float v1 = lrelu(acc1[u] + bs[u]);
            float v2 = lrelu(acc2[u] + bs[u]);
            float v3 = lrelu(acc3[u] + bs[u]);
            g_t2[(item0+0)*NU + u] = v0;
            g_t2[(item0+1)*NU + u] = v1;
            g_t2[(item0+2)*NU + u] = v2;
            g_t2[(item0+3)*NU + u] = v3;
            wt2[wid*4+0][u] = v0;
            wt2[wid*4+1][u] = v1;
            wt2[wid*4+2][u] = v2;
            wt2[wid*4+3][u] = v3;
        }
    }
    __syncthreads();
    if (t < NU){
        float s = 0.f, q = 0.f;
        #pragma unroll
        for (int w = 0; w < 32; w++){ float v = wt2[w][t]; s += v; q = fmaf(v, v, q); }
        g_bn2p[blockIdx.x*NU + t] = s;
        g_bn2q[blockIdx.x*NU + t] = q;
    }
}

// ---------------- K3: batched IPM, 32-thread blocks (16 items), rp-recurrence ----------------
#define HOFF0 0
#define HOFF1 1
#define HOFF2 2
#define HOFF3 4
#define HOFF4 6
#define HOFF5 9
#define HOFF6 12
#define HOFF7 16
#define HOFF8 20
#define HOFF9 25

template<int K>
__device__ __forceinline__ void passA_blk(const float* __restrict__ Gblk, int sa0, int hBase,
    float phi, u64* H2, u64* b1p, float smu,
    const float* s_sh, const float* l_sh, const float* h_sh)
{
    const int HOFF[10] = {HOFF0,HOFF1,HOFF2,HOFF3,HOFF4,HOFF5,HOFF6,HOFF7,HOFF8,HOFF9};
    const int KH = K/2;
    #pragma unroll 4
    for (int j = 0; j < 16; j++){
        const int sa = sa0 + j;
        float sm = s_sh[sa], lm = l_sh[sa];
        float ivs = frcp(sm);
        float w = lm*ivs;
        float rp = phi * h_sh[hBase + j];          // rp = phi*(1-h)
        float coef = fmaf(lm, rp, smu)*ivs;
        float2 gv[KH]; u64 g2[KH];
        #pragma unroll
        for (int jj = 0; jj < KH; jj++){
            gv[jj] = *(const float2*)&Gblk[j*K + 2*jj];
            g2[jj] = pk(gv[jj].x, gv[jj].y);
        }
        u64 w2v = pk(w, w), c2 = pk(coef, coef);
        u64 wgp[KH];
        #pragma unroll
        for (int jj = 0; jj < KH; jj++){
            wgp[jj] = mul2(w2v, g2[jj]);
            b1p[jj] = fma2(c2, g2[jj], b1p[jj]);
        }
        #pragma unroll
        for (int a = 0; a < K; a++){
            float ga = (a & 1) ? gv[a>>1].y : gv[a>>1].x;
            u64 ga2 = pk(ga, ga);
            #pragma unroll
            for (int pi = 0; pi <= (a>>1); pi++)
                H2[HOFF[a]+pi] = fma2(ga2, wgp[pi], H2[HOFF[a]+pi]);
        }
    }
}

template<int K>
__device__ __forceinline__ void passB1_blk(const float* __restrict__ Gblk, int sa0, int hBase,
    const u64* dz2, float phi, float smu, float& q,
    const float* s_sh, const float* l_sh, float* r_sh, const float* h_sh)
{
    const int KH = K/2;
    #pragma unroll 4
    for (int j = 0; j < 16; j++){
        const int sa = sa0 + j;
        float sm = s_sh[sa], lm = l_sh[sa];
        u64 acc = pk(0.f, 0.f);
        #pragma unroll
        for (int jj = 0; jj < KH; jj++){
            float2 gvj = *(const float2*)&Gblk[j*K + 2*jj];
            acc = fma2(pk(gvj.x, gvj.y), dz2[jj], acc);
        }
        float gx, gy; upk(acc, gx, gy);
        float ds = -fmaf(phi, h_sh[hBase + j], gx + gy);   // alpha-independent
        r_sh[sa] = ds;
        float ivsl = frcp(sm*lm);
        float r1 = -ds*lm*ivsl;
        float r2 = fmaf(fmaf(ds, lm, -smu), ivsl, 1.f);
        q = fmaxf(q, fmaxf(r1, r2));
    }
}

template<int K>
__device__ __forceinline__ void passB2_blk(int sa0,
    float smu, float alpha, float& msn,
    float* s_sh, float* l_sh, const float* r_sh)
{
    #pragma unroll 4
    for (int j = 0; j < 16; j++){
        const int sa = sa0 + j;
        float sm = s_sh[sa], lm = l_sh[sa];
        float ds = r_sh[sa];
        float rc = fmaf(sm, lm, -smu);
        float ivs = frcp(sm);
        float dlam = -fmaf(lm, ds, rc)*ivs;
        float sn = fmaf(alpha, ds, sm);
        float ln = fmaf(alpha, dlam, lm);
        s_sh[sa] = sn; l_sh[sa] = ln;
        msn = fmaf(sn, ln, msn);
    }
}

__global__ void __launch_bounds__(32, 7) ipm_kernel(float* __restrict__ out,
    const float* __restrict__ g2, const float* __restrict__ beta2)
{
    extern __shared__ float dyn[];
    float* s_sh = dyn;                    // IPB*SROW
    float* l_sh = dyn +   IPB*SROW;
    float* r_sh = dyn + 2*IPB*SROW;       // ds cache
    __shared__ __align__(8) float G_sh[704];
    __shared__ float h_sh[MI];            // holds (1 - h)
    __shared__ __align__(8) float Q_sh[NU*NU];
    __shared__ float ac_sh[2*NU];
    const int GA[4] = {0, 80, 224, 432};
    const int GB[4] = {48, 160, 336, 576};

    const int tid = threadIdx.x;          // 0..31 (one warp)
    const int r = tid & 1, q = tid >> 1;  // q in 0..15
    const int item = blockIdx.x*IPB + q;

    // ---- preamble: bn2 finalize (redundant per block; warp-shuffle reduce)
    {
        float loc[20];
        #pragma unroll
        for (int j = 0; j < 20; j++) loc[j] = 0.f;
        for (int b = tid; b < FC2_BLOCKS; b += 32){
            #pragma unroll
            for (int u = 0; u < NU; u++){
                loc[u]    += g_bn2p[b*NU + u];
                loc[10+u] += g_bn2q[b*NU + u];
            }
        }
        #pragma unroll
        for (int j = 0; j < 20; j++){
            #pragma unroll
            for (int off = 16; off > 0; off >>= 1)
                loc[j] += __shfl_xor_sync(0xffffffffu, loc[j], off);
        }
        if (tid < NU){
            float sv = 0.f, qv = 0.f;
            #pragma unroll
            for (int u = 0; u < NU; u++){
                if (tid == u){ sv = loc[u]; qv = loc[10+u]; }
            }
            float mu  = sv * (1.f/(float)NB);
            float var = qv * (1.f/(float)NB) - mu*mu;
            float a = g2[tid]*rsqrtf(var + 1e-5f);
            ac_sh[tid]      = a;
            ac_sh[NU + tid] = beta2[tid] - mu*a;
        }
    }

    // loads (32 threads)
    for (int mm = tid; mm < 128; mm += 32){
        int bi = mm >> 5, lr = mm & 31, hf = lr >> 4, j = lr & 15, K = 2*bi + 2;
        int base = (hf ? GB[bi] : GA[bi]) + j*K;
        for (int c = 0; c < K; c++) G_sh[base + c] = g_G[(10+mm)*NU + c];
    }
    for (int i = tid; i < MI; i += 32) h_sh[i] = 1.f - g_h[i];   // (1-h)
    for (int i = tid; i < 100; i += 32) Q_sh[i] = g_Qhat[i];
    __syncthreads();

    float p[NU];
    u64 z2[5];
    #pragma unroll
    for (int u = 0; u < NU; u++)
        p[u] = fmaf(g_t2[item*NU+u], ac_sh[u], ac_sh[NU+u]);
    #pragma unroll
    for (int j = 0; j < 5; j++) z2[j] = pk(0.f, 0.f);

    float s_id[5], l_id[5];
    #pragma unroll
    for (int j = 0; j < 5; j++){ s_id[j] = 1.f; l_id[j] = 1.f; }

    int saB[4], hB[4];
    const float* Gb[4];
    #pragma unroll
    for (int bi = 0; bi < 4; bi++){
        int mm0 = 32*bi + 16*r;
        saB[bi] = q*SROW + mm0;
        hB[bi]  = 10 + mm0;
        Gb[bi]  = &G_sh[r ? GB[bi] : GA[bi]];
        #pragma unroll 4
        for (int j = 0; j < 16; j++){
            s_sh[saB[bi]+j] = 1.f; l_sh[saB[bi]+j] = 1.f;
        }
    }
    float musum = (float)MI;
    float phi = 1.f;                       // prod(1-alpha)

    for (int it = 0; it < ITER; it++){
        float smu = musum * (SIGMA/(float)MI);
        u64 H2[30], b1p[5];
        #pragma unroll
        for (int e = 0; e < 30; e++) H2[e] = pk(0.f, 0.f);
        #pragma unroll
        for (int j = 0; j < 5; j++) b1p[j] = pk(0.f, 0.f);

        // identity rows: compile-time indices per parity branch
        if (r == 0){
            #pragma unroll
            for (int j = 0; j < 5; j++){
                const int m = j;
                float sm = s_id[j], lm = l_id[j];
                float ivs = frcp(sm);
                float w = lm*ivs;
                float rp = phi * h_sh[m];
                float c = fmaf(lm, rp, smu)*ivs;
                b1p[m/2] = add2(b1p[m/2], (m&1) ? pk(0.f,c) : pk(c,0.f));
                const int ho = (m==0?HOFF0:m==1?HOFF1:m==2?HOFF2:m==3?HOFF3:HOFF4) + m/2;
                H2[ho] = add2(H2[ho], (m&1) ? pk(0.f,w) : pk(w,0.f));
            }
        } else {
            #pragma unroll
            for (int j = 0; j < 5; j++){
                const int m = 5 + j;
                float sm = s_id[j], lm = l_id[j];
                float ivs = frcp(sm);
                float w = lm*ivs;
                float rp = phi * h_sh[m];
                float c = fmaf(lm, rp, smu)*ivs;
                b1p[m/2] = add2(b1p[m/2], (m&1) ? pk(0.f,c) : pk(c,0.f));
                const int ho = (m==5?HOFF5:m==6?HOFF6:m==7?HOFF7:m==8?HOFF8:HOFF9) + m/2;
                H2[ho] = add2(H2[ho], (m&1) ? pk(0.f,w) : pk(w,0.f));
            }
        }

        passA_blk<2>(Gb[0], saB[0], hB[0], phi, H2, b1p, smu, s_sh, l_sh, h_sh);
        passA_blk<4>(Gb[1], saB[1], hB[1], phi, H2, b1p, smu, s_sh, l_sh, h_sh);
        passA_blk<6>(Gb[2], saB[2], hB[2], phi, H2, b1p, smu, s_sh, l_sh, h_sh);
        passA_blk<8>(Gb[3], saB[3], hB[3], phi, H2, b1p, smu, s_sh, l_sh, h_sh);

        #pragma unroll
        for (int e = 0; e < 30; e++) H2[e] = add2(H2[e], sh64(H2[e]));
        #pragma unroll
        for (int j = 0; j < 5; j++) b1p[j] = add2(b1p[j], sh64(b1p[j]));

        const int HOFF[10] = {HOFF0,HOFF1,HOFF2,HOFF3,HOFF4,HOFF5,HOFF6,HOFF7,HOFF8,HOFF9};
        float Hs[55];
        #pragma unroll
        for (int a = 0; a < NU; a++){
            #pragma unroll
            for (int pi = 0; pi <= (a>>1); pi++){
                float x, y; upk(H2[HOFF[a]+pi], x, y);
                Hs[(a*(a+1))/2 + 2*pi] = x + Q_sh[a*NU + 2*pi];
                if (2*pi+1 <= a) Hs[(a*(a+1))/2 + 2*pi+1] = y + Q_sh[a*NU + 2*pi+1];
            }
        }
        float b1[NU];
        #pragma unroll
        for (int j = 0; j < 5; j++) upk(b1p[j], b1[2*j], b1[2*j+1]);

        float dz[NU];
        #pragma unroll
        for (int i = 0; i < NU; i++){
            u64 acc = pk(0.f, 0.f);
            #pragma unroll
            for (int j = 0; j < 5; j++){
                float2 qv = *(const float2*)&Q_sh[i*NU + 2*j];
                acc = fma2(pk(qv.x, qv.y), z2[j], acc);
            }
            float qx, qy; upk(acc, qx, qy);
            dz[i] = -(p[i] + b1[i] + qx + qy);
        }
        #pragma unroll
        for (int k = 0; k < NU; k++){
            float inv = rsqrtf(Hs[(k*(k+1))/2+k]);
            Hs[(k*(k+1))/2+k] = inv;
            #pragma unroll
            for (int i = k+1; i < NU; i++) Hs[(i*(i+1))/2+k] *= inv;
            #pragma unroll
            for (int j = k+1; j < NU; j++){
                float ljk = Hs[(j*(j+1))/2+k];
                #pragma unroll
                for (int i = j; i < NU; i++)
                    Hs[(i*(i+1))/2+j] = fmaf(-Hs[(i*(i+1))/2+k], ljk, Hs[(i*(i+1))/2+j]);
            }
        }
        #pragma unroll
        for (int i = 0; i < NU; i++){
            float tt = dz[i];
            #pragma unroll
            for (int j = 0; j < i; j++) tt = fmaf(-Hs[(i*(i+1))/2+j], dz[j], tt);
            dz[i] = tt * Hs[(i*(i+1))/2+i];
        }
        #pragma unroll
        for (int i = NU-1; i >= 0; i--){
            float tt = dz[i];
            #pragma unroll
            for (int j = i+1; j < NU; j++) tt = fmaf(-Hs[(j*(j+1))/2+i], dz[j], tt);
            dz[i] = tt * Hs[(i*(i+1))/2+i];
        }
        u64 dz2[5];
        #pragma unroll
        for (int j = 0; j < 5; j++) dz2[j] = pk(dz[2*j], dz[2*j+1]);

        // ---- pass B1: ds cached in r_sh; step-length ratios ----
        float qm = 0.f;
        if (r == 0){
            #pragma unroll
            for (int j = 0; j < 5; j++){
                const int m = j;
                float sm = s_id[j], lm = l_id[j];
                float ds = -fmaf(phi, h_sh[m], dz[m]);
                float ivsl = frcp(sm*lm);
                float r1 = -ds*lm*ivsl;
                float r2 = fmaf(fmaf(ds, lm, -smu), ivsl, 1.f);
                qm = fmaxf(qm, fmaxf(r1, r2));
            }
        } else {
            #pragma unroll
            for (int j = 0; j < 5; j++){
                const int m = 5 + j;
                float sm = s_id[j], lm = l_id[j];
                float ds = -fmaf(phi, h_sh[m], dz[m]);
                float ivsl = frcp(sm*lm);
                float r1 = -ds*lm*ivsl;
                float r2 = fmaf(fmaf(ds, lm, -smu), ivsl, 1.f);
                qm = fmaxf(qm, fmaxf(r1, r2));
            }
        }
        passB1_blk<2>(Gb[0], saB[0], hB[0], dz2, phi, smu, qm, s_sh, l_sh, r_sh, h_sh);
        passB1_blk<4>(Gb[1], saB[1], hB[1], dz2, phi, smu, qm, s_sh, l_sh, r_sh, h_sh);
        passB1_blk<6>(Gb[2], saB[2], hB[2], dz2, phi, smu, qm, s_sh, l_sh, r_sh, h_sh);
        passB1_blk<8>(Gb[3], saB[3], hB[3], dz2, phi, smu, qm, s_sh, l_sh, r_sh, h_sh);
        qm = fmaxf(qm, __shfl_xor_sync(0xffffffffu, qm, 1));
        float alpha = fminf(1.f, 0.99f*frcp(qm));

        // ---- pass B2: ds from r_sh; update s/lam; accumulate musum ----
        float msn = 0.f;
        if (r == 0){
            #pragma unroll
            for (int j = 0; j < 5; j++){
                const int m = j;
                float sm = s_id[j], lm = l_id[j];
                float ds = -fmaf(phi, h_sh[m], dz[m]);
                float rc = fmaf(sm, lm, -smu);
                float ivs = frcp(sm);
                float dlam = -fmaf(lm, ds, rc)*ivs;
                float sn = fmaf(alpha, ds, sm);
                float ln = fmaf(alpha, dlam, lm);
                s_id[j] = sn; l_id[j] = ln;
                msn = fmaf(sn, ln, msn);
            }
        } else {
            #pragma unroll
            for (int j = 0; j < 5; j++){
                const int m = 5 + j;
                float sm = s_id[j], lm = l_id[j];
                float ds = -fmaf(phi, h_sh[m], dz[m]);
                float rc = fmaf(sm, lm, -smu);
                float ivs = frcp(sm);
                float dlam = -fmaf(lm, ds, rc)*ivs;
                float sn = fmaf(alpha, ds, sm);
                float ln = fmaf(alpha, dlam, lm);
                s_id[j] = sn; l_id[j] = ln;
                msn = fmaf(sn, ln, msn);
            }
        }
        passB2_blk<2>(saB[0], smu, alpha, msn, s_sh, l_sh, r_sh);
        passB2_blk<4>(saB[1], smu, alpha, msn, s_sh, l_sh, r_sh);
        passB2_blk<6>(saB[2], smu, alpha, msn, s_sh, l_sh, r_sh);
        passB2_blk<8>(saB[3], smu, alpha, msn, s_sh, l_sh, r_sh);
        msn += __shfl_xor_sync(0xffffffffu, msn, 1);
        musum = msn;

        phi *= (1.f - alpha);              // rp recurrence
        u64 al2 = pk(alpha, alpha);
        #pragma unroll
        for (int j = 0; j < 5; j++) z2[j] = fma2(al2, dz2[j], z2[j]);
    }
    if (r == 0){
        float z0, z1; upk(z2[0], z0, z1);
        out[item] = z0;
    }
}

// ---------------- launch (4 launches; ipm at index 3 for ncu capture) ----------------
extern "C" void kernel_launch(void* const* d_in, const int* in_sizes, int n_in,
                              void* d_out, int out_size)
{
    (void)in_sizes; (void)n_in; (void)out_size;
    const float* x    = (const float*)d_in[0];
    const float* w1   = (const float*)d_in[1];
    const float* b1   = (const float*)d_in[2];
    const float* w2   = (const float*)d_in[3];
    const float* b2   = (const float*)d_in[4];
    const float* bn1g = (const float*)d_in[5];
    const float* bn1b = (const float*)d_in[6];
    const float* bn2g = (const float*)d_in[7];
    const float* bn2b = (const float*)d_in[8];
    const float* L    = (const float*)d_in[9];
    const float* LP   = (const float*)d_in[10];
    const float* LR   = (const float*)d_in[11];
    const float* A    = (const float*)d_in[12];
    const float* Bm   = (const float*)d_in[13];
    const float* u0   = (const float*)d_in[14];
    const float* s0   = (const float*)d_in[15];
    float* out = (float*)d_out;

    const int ipm_smem = 3*IPB*SROW*(int)sizeof(float);   // 24,768 B
    cudaFuncSetAttribute(ipm_kernel, cudaFuncAttributeMaxDynamicSharedMemorySize, ipm_smem);

    fc1qp_kernel<<<129, 256>>>(x, w1, b1, L, LP, LR, A, Bm, u0, s0);  // 0
    fold_all<<<NU, 256>>>(w2, b2, bn1g, bn1b);                        // 1
    fc2_kernel<<<NB/32, 256>>>();                                     // 2
    ipm_kernel<<<NB/IPB, 32, ipm_smem>>>(out, bn2g, bn2b);            // 3
}

// round 16
// speedup vs baseline: 1.1102x; 1.0466x over previous
#include <cuda_runtime.h>

#define NB   16384
#define NH   1024
#define NIN  32
#define NU   10
#define MI   138
#define ITER 30
#define SIGMA 0.1f
#define FC1_BLOCKS 128
#define FC2_BLOCKS (NB/32)    // 512

#define IPB  16               // items per IPM block (32 threads, 2 per item)
#define SROW 129              // odd stride -> conflict-free pair access

typedef unsigned long long u64;

// ---------------- device scratch (static, no allocs) ----------------
__device__ float g_h1[NB*NH];              // 64 MB, row-major [item][feature]
__device__ float g_bn1p[FC1_BLOCKS*NH];
__device__ float g_bn1q[FC1_BLOCKS*NH];
__device__ float g_W2f[NU*NH];
__device__ float g_b2f[NU];
__device__ float g_t2[NB*NU];
__device__ float g_bn2p[FC2_BLOCKS*NU];
__device__ float g_bn2q[FC2_BLOCKS*NU];
__device__ float g_Qhat[NU*NU];
__device__ float g_G[MI*NU];
__device__ float g_h[MI];

__device__ __forceinline__ float frcp(float x){ float r; asm("rcp.approx.f32 %0, %1;" : "=f"(r) : "f"(x)); return r; }
__device__ __forceinline__ float lrelu(float v){ return v > 0.f ? v : 0.2f*v; }

// ---- packed f32x2 helpers ----
__device__ __forceinline__ u64 pk(float x, float y){
    u64 r; asm("mov.b64 %0, {%1,%2};" : "=l"(r) : "f"(x), "f"(y)); return r;
}
__device__ __forceinline__ void upk(u64 v, float& x, float& y){
    asm("mov.b64 {%0,%1}, %2;" : "=f"(x), "=f"(y) : "l"(v));
}
__device__ __forceinline__ u64 fma2(u64 a, u64 b, u64 c){
    u64 d; asm("fma.rn.f32x2 %0, %1, %2, %3;" : "=l"(d) : "l"(a), "l"(b), "l"(c)); return d;
}
__device__ __forceinline__ u64 mul2(u64 a, u64 b){
    u64 d; asm("mul.rn.f32x2 %0, %1, %2;" : "=l"(d) : "l"(a), "l"(b)); return d;
}
__device__ __forceinline__ u64 add2(u64 a, u64 b){
    u64 d; asm("add.rn.f32x2 %0, %1, %2;" : "=l"(d) : "l"(a), "l"(b)); return d;
}
__device__ __forceinline__ u64 sh64(u64 v){
    return __shfl_xor_sync(0xffffffffu, v, 1);
}

// ---------------- K0: fc1 (blocks 0..127, f32x2 inner) + build_qp (block 128) ----------------
__global__ void __launch_bounds__(256) fc1qp_kernel(
    const float* __restrict__ x,  const float* __restrict__ W1, const float* __restrict__ b1,
    const float* __restrict__ L,  const float* __restrict__ LP, const float* __restrict__ LR,
    const float* __restrict__ A,  const float* __restrict__ Bm,
    const float* __restrict__ u0, const float* __restrict__ s0)
{
    __shared__ __align__(16) float sh[5120];
    const int t = threadIdx.x;

    if (blockIdx.x < 128){
        // ================= fc1 (f32x2 packed dot) =================
        float* xs = sh;
        const int row0 = blockIdx.x * 128;
        {
            const float4* src = (const float4*)(x + row0*32);
            float4* dst = (float4*)xs;
            for (int e = t; e < 1024; e += 256) dst[e] = src[e];
        }
        __syncthreads();
        #pragma unroll
        for (int ff = 0; ff < 4; ff++){
            const int f = t + ff*256;
            u64 w2[16];
            const float4* wp = (const float4*)(W1 + f*32);
            #pragma unroll
            for (int k = 0; k < 8; k++){
                float4 v = wp[k];
                w2[2*k+0] = pk(v.x, v.y);
                w2[2*k+1] = pk(v.z, v.w);
            }
            const float bias = b1[f];
            float sum = 0.f, sq = 0.f;
            for (int r = 0; r < 128; r++){
                const ulonglong2* xp = (const ulonglong2*)(xs + r*32);
                u64 accA = pk(bias, 0.f), accB = pk(0.f, 0.f);
                #pragma unroll
                for (int kk = 0; kk < 8; kk++){
                    ulonglong2 xv = xp[kk];
                    accA = fma2(w2[2*kk+0], xv.x, accA);
                    accB = fma2(w2[2*kk+1], xv.y, accB);
                }
                float a0, a1v; upk(add2(accA, accB), a0, a1v);
                float v = lrelu(a0 + a1v);
                g_h1[(row0+r)*NH + f] = v;
                sum += v; sq = fmaf(v, v, sq);
            }
            g_bn1p[blockIdx.x*NH + f] = sum;
            g_bn1q[blockIdx.x*NH + f] = sq;
        }
        return;
    }

    // ================= build_qp (block 128) =================
    float* Q  = sh;            // 1024
    float* P  = sh + 1024;     // 1024
    float* Bh = sh + 2048;     // 1280
    float* Ms = sh + 3328;     // 1280
    float* pw = sh + 4608;     // 256 (4 x 64)
    float* R  = sh + 4864;     // 4

    for (int e = t; e < 1024; e += 256){
        int i = e >> 5, j = e & 31;
        int kmax = i < j ? i : j;
        float aq = (i==j) ? 1e-4f : 0.f;
        float ap = aq;
        for (int k = 0; k <= kmax; k++){
            aq = fmaf(L [i*32+k], L [j*32+k], aq);
            ap = fmaf(LP[i*32+k], LP[j*32+k], ap);
        }
        Q[e] = aq; P[e] = ap;
    }
    if (t < 4){
        int i = t >> 1, j = t & 1;
        int kmax = i < j ? i : j;
        float a = (i==j) ? 1e-4f : 0.f;
        for (int k = 0; k <= kmax; k++) a = fmaf(LR[i*2+k], LR[j*2+k], a);
        R[t] = a;
    }
    if (t < 64) pw[t] = Bm[t];
    __syncthreads();
    for (int s = 1; s < 4; s++){
        if (t < 64){
            int r = t >> 1, c = t & 1;
            float acc = 0.f;
            for (int k = 0; k < 32; k++) acc = fmaf(A[r*32+k], pw[(s-1)*64 + k*2+c], acc);
            pw[s*64 + t] = acc;
        }
        __syncthreads();
    }
    for (int e = t; e < 128*NU; e += 256){
        int row = e / NU, col = e - row*NU;
        int bi = row >> 5, r = row & 31, bj = col >> 1, c = col & 1;
        Bh[e] = (bj <= bi) ? pw[(bi-bj)*64 + r*2+c] : 0.f;
    }
    __syncthreads();
    for (int e = t; e < 128*NU; e += 256){
        int row = e / NU, col = e - row*NU;
        int b = row >> 5, r = row & 31;
        const float* Qb = (b < 3) ? Q : P;
        float acc = 0.f;
        for (int k = 0; k < 32; k++) acc = fmaf(Qb[r*32+k], Bh[(b*32+k)*NU+col], acc);
        Ms[e] = acc;
    }
    __syncthreads();
    if (t < 100){
        int a = t / NU, b = t - (t/NU)*NU;
        float acc = ((a>>1) == (b>>1)) ? R[(a&1)*2+(b&1)] : 0.f;
        for (int row = 0; row < 128; row++) acc = fmaf(Bh[row*NU+a], Ms[row*NU+b], acc);
        g_Qhat[t] = acc;
    }
    for (int e = t; e < MI*NU; e += 256){
        int row = e / NU, col = e - (e/NU)*NU;
        g_G[e] = (row < NU) ? ((row==col) ? 1.f : 0.f) : Bh[(row-NU)*NU+col];
    }
    if (t < MI){
        float acc = s0[t];
        if (t < NU) acc += u0[t];
        else { for (int j = 0; j < NU; j++) acc = fmaf(Bh[(t-NU)*NU+j], u0[j], acc); }
        g_h[t] = acc;
    }
}

// ---------------- K1: bn1 finalize fused with fc2-weight fold (1024 threads) ----------------
__global__ void __launch_bounds__(1024) fold_all(const float* __restrict__ W2, const float* __restrict__ b2,
                         const float* __restrict__ g1, const float* __restrict__ beta1)
{
    __shared__ float red[1024];
    const int u = blockIdx.x, t = threadIdx.x;
    float dot = 0.f;
    for (int k = t; k < NH; k += 1024){
        float sum = 0.f, sq = 0.f;
        for (int b = 0; b < FC1_BLOCKS; b++){
            sum += g_bn1p[b*NH + k];
            sq  += g_bn1q[b*NH + k];
        }
        float mu  = sum * (1.f/(float)NB);
        float var = sq  * (1.f/(float)NB) - mu*mu;
        float a = g1[k]*rsqrtf(var + 1e-5f);
        float c = beta1[k] - mu*a;
        float wv = W2[u*NH + k];
        g_W2f[u*NH + k] = wv * a;
        dot = fmaf(wv, c, dot);
    }
    red[t] = dot; __syncthreads();
    for (int s = 512; s > 0; s >>= 1){
        if (t < s) red[t] += red[t+s];
        __syncthreads();
    }
    if (t == 0) g_b2f[u] = b2[u] + red[0];
}

// ---------------- K2: fc2 (4 items per warp) + leaky_relu + bn2 stats ----------------
__global__ void __launch_bounds__(256) fc2_kernel()
{
    __shared__ float Ws[NU*NH];
    __shared__ float bs[NU];
    __shared__ float wt2[32][NU];
    const int t = threadIdx.x, lane = t & 31, wid = t >> 5;
    for (int e = t; e < NU*NH; e += 256) Ws[e] = g_W2f[e];
    if (t < NU) bs[t] = g_b2f[t];
    __syncthreads();
    const int item0 = blockIdx.x*32 + wid*4;
    float acc0[NU], acc1[NU], acc2[NU], acc3[NU];
    #pragma unroll
    for (int u = 0; u < NU; u++){ acc0[u]=0.f; acc1[u]=0.f; acc2[u]=0.f; acc3[u]=0.f; }
    const float* h0 = g_h1 + item0*NH;
    const float* h1r = h0 + NH;
    const float* h2r = h0 + 2*NH;
    const float* h3r = h0 + 3*NH;
    for (int j = 0; j < 32; j++){
        float v0 = h0[j*32 + lane];
        float v1 = h1r[j*32 + lane];
        float v2 = h2r[j*32 + lane];
        float v3 = h3r[j*32 + lane];
        #pragma unroll
        for (int u = 0; u < NU; u++){
            float wv = Ws[u*NH + j*32 + lane];
            acc0[u] = fmaf(v0, wv, acc0[u]);
            acc1[u] = fmaf(v1, wv, acc1[u]);
            acc2[u] = fmaf(v2, wv, acc2[u]);
            acc3[u] = fmaf(v3, wv, acc3[u]);
        }
    }
    #pragma unroll
    for (int u = 0; u < NU; u++){
        #pragma unroll
        for (int off = 16; off > 0; off >>= 1){
            acc0[u] += __shfl_xor_sync(0xffffffffu, acc0[u], off);
            acc1[u] += __shfl_xor_sync(0xffffffffu, acc1[u], off);
            acc2[u] += __shfl_xor_sync(0xffffffffu, acc2[u], off);
            acc3[u] += __shfl_xor_sync(0xffffffffu, acc3[u], off);
        }
    }
    if (lane == 0){
        #pragma unroll
        for (int u = 0; u < NU; u++){
            float v0 = lrelu(acc0[u] + bs[u]);
            float v1 = lrelu(acc1[u] + bs[u]);
            float v2 = lrelu(acc2[u] + bs[u]);
            float v3 = lrelu(acc3[u] + bs[u]);
            g_t2[(item0+0)*NU + u] = v0;
            g_t2[(item0+1)*NU + u] = v1;
            g_t2[(item0+2)*NU + u] = v2;
            g_t2[(item0+3)*NU + u] = v3;
            wt2[wid*4+0][u] = v0;
            wt2[wid*4+1][u] = v1;
            wt2[wid*4+2][u] = v2;
            wt2[wid*4+3][u] = v3;
        }
    }
    __syncthreads();
    if (t < NU){
        float s = 0.f, q = 0.f;
        #pragma unroll
        for (int w = 0; w < 32; w++){ float v = wt2[w][t]; s += v; q = fmaf(v, v, q); }
        g_bn2p[blockIdx.x*NU + t] = s;
        g_bn2q[blockIdx.x*NU + t] = q;
    }
}

// ---------------- K3: batched IPM, 32-thread blocks (16 items), rp-recurrence ----------------
// G stored packed as u64 pairs in shared.
#define HOFF0 0
#define HOFF1 1
#define HOFF2 2
#define HOFF3 4
#define HOFF4 6
#define HOFF5 9
#define HOFF6 12
#define HOFF7 16
#define HOFF8 20
#define HOFF9 25

template<int K>
__device__ __forceinline__ void passA_blk(const u64* __restrict__ Gblk, int sa0, int hBase,
    float phi, u64* H2, u64* b1p, float smu,
    const float* s_sh, const float* l_sh, const float* h_sh)
{
    const int HOFF[10] = {HOFF0,HOFF1,HOFF2,HOFF3,HOFF4,HOFF5,HOFF6,HOFF7,HOFF8,HOFF9};
    const int KH = K/2;
    #pragma unroll 4
    for (int j = 0; j < 16; j++){
        const int sa = sa0 + j;
        float sm = s_sh[sa], lm = l_sh[sa];
        float ivs = frcp(sm);
        float w = lm*ivs;
        float rp = phi * h_sh[hBase + j];          // rp = phi*(1-h)
        float coef = fmaf(lm, rp, smu)*ivs;
        u64 g2[KH]; float gx_[KH], gy_[KH];
        #pragma unroll
        for (int jj = 0; jj < KH; jj++){
            g2[jj] = Gblk[j*KH + jj];
            upk(g2[jj], gx_[jj], gy_[jj]);
        }
        u64 w2v = pk(w, w), c2 = pk(coef, coef);
        u64 wgp[KH];
        #pragma unroll
        for (int jj = 0; jj < KH; jj++){
            wgp[jj] = mul2(w2v, g2[jj]);
            b1p[jj] = fma2(c2, g2[jj], b1p[jj]);
        }
        #pragma unroll
        for (int a = 0; a < K; a++){
            float ga = (a & 1) ? gy_[a>>1] : gx_[a>>1];
            u64 ga2 = pk(ga, ga);
            #pragma unroll
            for (int pi = 0; pi <= (a>>1); pi++)
                H2[HOFF[a]+pi] = fma2(ga2, wgp[pi], H2[HOFF[a]+pi]);
        }
    }
}

template<int K>
__device__ __forceinline__ void passB1_blk(const u64* __restrict__ Gblk, int sa0, int hBase,
    const u64* dz2, float phi, float smu, float& q,
    const float* s_sh, const float* l_sh, float* r_sh, const float* h_sh)
{
    const int KH = K/2;
    #pragma unroll 4
    for (int j = 0; j < 16; j++){
        const int sa = sa0 + j;
        float sm = s_sh[sa], lm = l_sh[sa];
        u64 acc = pk(0.f, 0.f);
        #pragma unroll
        for (int jj = 0; jj < KH; jj++)
            acc = fma2(Gblk[j*KH + jj], dz2[jj], acc);
        float gx, gy; upk(acc, gx, gy);
        float ds = -fmaf(phi, h_sh[hBase + j], gx + gy);   // alpha-independent
        r_sh[sa] = ds;
        float ivsl = frcp(sm*lm);
        float r1 = -ds*lm*ivsl;
        float r2 = fmaf(fmaf(ds, lm, -smu), ivsl, 1.f);
        q = fmaxf(q, fmaxf(r1, r2));
    }
}

template<int K>
__device__ __forceinline__ void passB2_blk(int sa0,
    float smu, float alpha, float& msn,
    float* s_sh, float* l_sh, const float* r_sh)
{
    #pragma unroll 4
    for (int j = 0; j < 16; j++){
        const int sa = sa0 + j;
        float sm = s_sh[sa], lm = l_sh[sa];
        float ds = r_sh[sa];
        float rc = fmaf(sm, lm, -smu);
        float ivs = frcp(sm);
        float dlam = -fmaf(lm, ds, rc)*ivs;
        float sn = fmaf(alpha, ds, sm);
        float ln = fmaf(alpha, dlam, lm);
        s_sh[sa] = sn; l_sh[sa] = ln;
        msn = fmaf(sn, ln, msn);
    }
}

__global__ void __launch_bounds__(32, 7) ipm_kernel(float* __restrict__ out,
    const float* __restrict__ g2w, const float* __restrict__ beta2)
{
    extern __shared__ float dyn[];
    float* s_sh = dyn;                    // IPB*SROW
    float* l_sh = dyn +   IPB*SROW;
    float* r_sh = dyn + 2*IPB*SROW;       // ds cache
    __shared__ __align__(16) u64 G2_sh[352];
    __shared__ float h_sh[MI];            // holds (1 - h)
    __shared__ __align__(8) float Q_sh[NU*NU];
    __shared__ float ac_sh[2*NU];
    const int GA2[4] = {0, 40, 112, 216};
    const int GB2[4] = {24, 80, 168, 288};

    const int tid = threadIdx.x;          // 0..31 (one warp)
    const int r = tid & 1, q = tid >> 1;  // q in 0..15
    const int item = blockIdx.x*IPB + q;

    // ---- preamble: bn2 finalize (redundant per block; warp-shuffle reduce)
    {
        float loc[20];
        #pragma unroll
        for (int j = 0; j < 20; j++) loc[j] = 0.f;
        for (int b = tid; b < FC2_BLOCKS; b += 32){
            #pragma unroll
            for (int u = 0; u < NU; u++){
                loc[u]    += g_bn2p[b*NU + u];
                loc[10+u] += g_bn2q[b*NU + u];
            }
        }
        #pragma unroll
        for (int j = 0; j < 20; j++){
            #pragma unroll
            for (int off = 16; off > 0; off >>= 1)
                loc[j] += __shfl_xor_sync(0xffffffffu, loc[j], off);
        }
        if (tid < NU){
            float sv = 0.f, qv = 0.f;
            #pragma unroll
            for (int u = 0; u < NU; u++){
                if (tid == u){ sv = loc[u]; qv = loc[10+u]; }
            }
            float mu  = sv * (1.f/(float)NB);
            float var = qv * (1.f/(float)NB) - mu*mu;
            float a = g2w[tid]*rsqrtf(var + 1e-5f);
            ac_sh[tid]      = a;
            ac_sh[NU + tid] = beta2[tid] - mu*a;
        }
    }

    // loads (32 threads); pack G pairs into u64
    for (int mm = tid; mm < 128; mm += 32){
        int bi = mm >> 5, lr = mm & 31, hf = lr >> 4, j = lr & 15, K = 2*bi + 2;
        int base2 = (hf ? GB2[bi] : GA2[bi]) + j*(K/2);
        const float* src = &g_G[(10+mm)*NU];
        for (int c2 = 0; c2 < K/2; c2++)
            G2_sh[base2 + c2] = pk(src[2*c2], src[2*c2+1]);
    }
    for (int i = tid; i < MI; i += 32) h_sh[i] = 1.f - g_h[i];   // (1-h)
    for (int i = tid; i < 100; i += 32) Q_sh[i] = g_Qhat[i];
    __syncthreads();

    float p[NU];
    u64 z2[5];
    #pragma unroll
    for (int u = 0; u < NU; u++)
        p[u] = fmaf(g_t2[item*NU+u], ac_sh[u], ac_sh[NU+u]);
    #pragma unroll
    for (int j = 0; j < 5; j++) z2[j] = pk(0.f, 0.f);

    float s_id[5], l_id[5];
    #pragma unroll
    for (int j = 0; j < 5; j++){ s_id[j] = 1.f; l_id[j] = 1.f; }

    int saB[4], hB[4];
    const u64* Gb[4];
    #pragma unroll
    for (int bi = 0; bi < 4; bi++){
        int mm0 = 32*bi + 16*r;
        saB[bi] = q*SROW + mm0;
        hB[bi]  = 10 + mm0;
        Gb[bi]  = &G2_sh[r ? GB2[bi] : GA2[bi]];
        #pragma unroll 4
        for (int j = 0; j < 16; j++){
            s_sh[saB[bi]+j] = 1.f; l_sh[saB[bi]+j] = 1.f;
        }
    }
    float musum = (float)MI;
    float phi = 1.f;                       // prod(1-alpha)

    for (int it = 0; it < ITER; it++){
        float smu = musum * (SIGMA/(float)MI);
        u64 H2[30], b1p[5];
        #pragma unroll
        for (int e = 0; e < 30; e++) H2[e] = pk(0.f, 0.f);
        #pragma unroll
        for (int j = 0; j < 5; j++) b1p[j] = pk(0.f, 0.f);

        // identity rows: compile-time indices per parity branch
        if (r == 0){
            #pragma unroll
            for (int j = 0; j < 5; j++){
                const int m = j;
                float sm = s_id[j], lm = l_id[j];
                float ivs = frcp(sm);
                float w = lm*ivs;
                float rp = phi * h_sh[m];
                float c = fmaf(lm, rp, smu)*ivs;
                b1p[m/2] = add2(b1p[m/2], (m&1) ? pk(0.f,c) : pk(c,0.f));
                const int ho = (m==0?HOFF0:m==1?HOFF1:m==2?HOFF2:m==3?HOFF3:HOFF4) + m/2;
                H2[ho] = add2(H2[ho], (m&1) ? pk(0.f,w) : pk(w,0.f));
            }
        } else {
            #pragma unroll
            for (int j = 0; j < 5; j++){
                const int m = 5 + j;
                float sm = s_id[j], lm = l_id[j];
                float ivs = frcp(sm);
                float w = lm*ivs;
                float rp = phi * h_sh[m];
                float c = fmaf(lm, rp, smu)*ivs;
                b1p[m/2] = add2(b1p[m/2], (m&1) ? pk(0.f,c) : pk(c,0.f));
                const int ho = (m==5?HOFF5:m==6?HOFF6:m==7?HOFF7:m==8?HOFF8:HOFF9) + m/2;
                H2[ho] = add2(H2[ho], (m&1) ? pk(0.f,w) : pk(w,0.f));
            }
        }

        passA_blk<2>(Gb[0], saB[0], hB[0], phi, H2, b1p, smu, s_sh, l_sh, h_sh);
        passA_blk<4>(Gb[1], saB[1], hB[1], phi, H2, b1p, smu, s_sh, l_sh, h_sh);
        passA_blk<6>(Gb[2], saB[2], hB[2], phi, H2, b1p, smu, s_sh, l_sh, h_sh);
        passA_blk<8>(Gb[3], saB[3], hB[3], phi, H2, b1p, smu, s_sh, l_sh, h_sh);

        #pragma unroll
        for (int e = 0; e < 30; e++) H2[e] = add2(H2[e], sh64(H2[e]));
        #pragma unroll
        for (int j = 0; j < 5; j++) b1p[j] = add2(b1p[j], sh64(b1p[j]));

        const int HOFF[10] = {HOFF0,HOFF1,HOFF2,HOFF3,HOFF4,HOFF5,HOFF6,HOFF7,HOFF8,HOFF9};
        float Hs[55];
        #pragma unroll
        for (int a = 0; a < NU; a++){
            #pragma unroll
            for (int pi = 0; pi <= (a>>1); pi++){
                float x, y; upk(H2[HOFF[a]+pi], x, y);
                Hs[(a*(a+1))/2 + 2*pi] = x + Q_sh[a*NU + 2*pi];
                if (2*pi+1 <= a) Hs[(a*(a+1))/2 + 2*pi+1] = y + Q_sh[a*NU + 2*pi+1];
            }
        }
        float b1[NU];
        #pragma unroll
        for (int j = 0; j < 5; j++) upk(b1p[j], b1[2*j], b1[2*j+1]);

        float dz[NU];
        #pragma unroll
        for (int i = 0; i < NU; i++){
            u64 acc = pk(0.f, 0.f);
            #pragma unroll
            for (int j = 0; j < 5; j++){
                float2 qv = *(const float2*)&Q_sh[i*NU + 2*j];
                acc = fma2(pk(qv.x, qv.y), z2[j], acc);
            }
            float qx, qy; upk(acc, qx, qy);
            dz[i] = -(p[i] + b1[i] + qx + qy);
        }
        #pragma unroll
        for (int k = 0; k < NU; k++){
            float inv = rsqrtf(Hs[(k*(k+1))/2+k]);
            Hs[(k*(k+1))/2+k] = inv;
            #pragma unroll
            for (int i = k+1; i < NU; i++) Hs[(i*(i+1))/2+k] *= inv;
            #pragma unroll
            for (int j = k+1; j < NU; j++){
                float ljk = Hs[(j*(j+1))/2+k];
                #pragma unroll
                for (int i = j; i < NU; i++)
                    Hs[(i*(i+1))/2+j] = fmaf(-Hs[(i*(i+1))/2+k], ljk, Hs[(i*(i+1))/2+j]);
            }
        }
        #pragma unroll
        for (int i = 0; i < NU; i++){
            float tt = dz[i];
            #pragma unroll
            for (int j = 0; j < i; j++) tt = fmaf(-Hs[(i*(i+1))/2+j], dz[j], tt);
            dz[i] = tt * Hs[(i*(i+1))/2+i];
        }
        #pragma unroll
        for (int i = NU-1; i >= 0; i--){
            float tt = dz[i];
            #pragma unroll
            for (int j = i+1; j < NU; j++) tt = fmaf(-Hs[(j*(j+1))/2+i], dz[j], tt);
            dz[i] = tt * Hs[(i*(i+1))/2+i];
        }
        u64 dz2[5];
        #pragma unroll
        for (int j = 0; j < 5; j++) dz2[j] = pk(dz[2*j], dz[2*j+1]);

        // ---- pass B1: ds cached in r_sh; step-length ratios ----
        float qm = 0.f;
        if (r == 0){
            #pragma unroll
            for (int j = 0; j < 5; j++){
                const int m = j;
                float sm = s_id[j], lm = l_id[j];
                float ds = -fmaf(phi, h_sh[m], dz[m]);
                float ivsl = frcp(sm*lm);
                float r1 = -ds*lm*ivsl;
                float r2 = fmaf(fmaf(ds, lm, -smu), ivsl, 1.f);
                qm = fmaxf(qm, fmaxf(r1, r2));
            }
        } else {
            #pragma unroll
            for (int j = 0; j < 5; j++){
                const int m = 5 + j;
                float sm = s_id[j], lm = l_id[j];
                float ds = -fmaf(phi, h_sh[m], dz[m]);
                float ivsl = frcp(sm*lm);
                float r1 = -ds*lm*ivsl;
                float r2 = fmaf(fmaf(ds, lm, -smu), ivsl, 1.f);
                qm = fmaxf(qm, fmaxf(r1, r2));
            }
        }
        passB1_blk<2>(Gb[0], saB[0], hB[0], dz2, phi, smu, qm, s_sh, l_sh, r_sh, h_sh);
        passB1_blk<4>(Gb[1], saB[1], hB[1], dz2, phi, smu, qm, s_sh, l_sh, r_sh, h_sh);
        passB1_blk<6>(Gb[2], saB[2], hB[2], dz2, phi, smu, qm, s_sh, l_sh, r_sh, h_sh);
        passB1_blk<8>(Gb[3], saB[3], hB[3], dz2, phi, smu, qm, s_sh, l_sh, r_sh, h_sh);
        qm = fmaxf(qm, __shfl_xor_sync(0xffffffffu, qm, 1));
        float alpha = fminf(1.f, 0.99f*frcp(qm));

        // ---- pass B2: ds from r_sh; update s/lam; accumulate musum ----
        float msn = 0.f;
        if (r == 0){
            #pragma unroll
            for (int j = 0; j < 5; j++){
                const int m = j;
                float sm = s_id[j], lm = l_id[j];
                float ds = -fmaf(phi, h_sh[m], dz[m]);
                float rc = fmaf(sm, lm, -smu);
                float ivs = frcp(sm);
                float dlam = -fmaf(lm, ds, rc)*ivs;
                float sn = fmaf(alpha, ds, sm);
                float ln = fmaf(alpha, dlam, lm);
                s_id[j] = sn; l_id[j] = ln;
                msn = fmaf(sn, ln, msn);
            }
        } else {
            #pragma unroll
            for (int j = 0; j < 5; j++){
                const int m = 5 + j;
                float sm = s_id[j], lm = l_id[j];
                float ds = -fmaf(phi, h_sh[m], dz[m]);
                float rc = fmaf(sm, lm, -smu);
                float ivs = frcp(sm);
                float dlam = -fmaf(lm, ds, rc)*ivs;
                float sn = fmaf(alpha, ds, sm);
                float ln = fmaf(alpha, dlam, lm);
                s_id[j] = sn; l_id[j] = ln;
                msn = fmaf(sn, ln, msn);
            }
        }
        passB2_blk<2>(saB[0], smu, alpha, msn, s_sh, l_sh, r_sh);
        passB2_blk<4>(saB[1], smu, alpha, msn, s_sh, l_sh, r_sh);
        passB2_blk<6>(saB[2], smu, alpha, msn, s_sh, l_sh, r_sh);
        passB2_blk<8>(saB[3], smu, alpha, msn, s_sh, l_sh, r_sh);
        msn += __shfl_xor_sync(0xffffffffu, msn, 1);
        musum = msn;

        phi *= (1.f - alpha);              // rp recurrence
        u64 al2 = pk(alpha, alpha);
        #pragma unroll
        for (int j = 0; j < 5; j++) z2[j] = fma2(al2, dz2[j], z2[j]);
    }
    if (r == 0){
        float z0, z1; upk(z2[0], z0, z1);
        out[item] = z0;
    }
}

// ---------------- launch (4 launches; ipm at index 3 for ncu capture) ----------------
extern "C" void kernel_launch(void* const* d_in, const int* in_sizes, int n_in,
                              void* d_out, int out_size)
{
    (void)in_sizes; (void)n_in; (void)out_size;
    const float* x    = (const float*)d_in[0];
    const float* w1   = (const float*)d_in[1];
    const float* b1   = (const float*)d_in[2];
    const float* w2   = (const float*)d_in[3];
    const float* b2   = (const float*)d_in[4];
    const float* bn1g = (const float*)d_in[5];
    const float* bn1b = (const float*)d_in[6];
    const float* bn2g = (const float*)d_in[7];
    const float* bn2b = (const float*)d_in[8];
    const float* L    = (const float*)d_in[9];
    const float* LP   = (const float*)d_in[10];
    const float* LR   = (const float*)d_in[11];
    const float* A    = (const float*)d_in[12];
    const float* Bm   = (const float*)d_in[13];
    const float* u0   = (const float*)d_in[14];
    const float* s0   = (const float*)d_in[15];
    float* out = (float*)d_out;

    const int ipm_smem = 3*IPB*SROW*(int)sizeof(float);   // 24,768 B
    cudaFuncSetAttribute(ipm_kernel, cudaFuncAttributeMaxDynamicSharedMemorySize, ipm_smem);

    fc1qp_kernel<<<129, 256>>>(x, w1, b1, L, LP, LR, A, Bm, u0, s0);  // 0
    fold_all<<<NU, 1024>>>(w2, b2, bn1g, bn1b);                       // 1
    fc2_kernel<<<NB/32, 256>>>();                                     // 2
    ipm_kernel<<<NB/IPB, 32, ipm_smem>>>(out, bn2g, bn2b);            // 3
}